// round 1
// baseline (speedup 1.0000x reference)
#include <cuda_runtime.h>
#include <cuda_bf16.h>
#include <math.h>

// ---------------- problem constants ----------------
#define NN   3                 // nodes
#define BB   4                 // batch
#define CC   256               // channels
#define HH   40
#define WW   40
#define PP   (HH*WW)           // 1600 pixels
#define EE   6                 // directed edges
#define NBB  (NN*BB)           // 12
#define CP   (CC*PP)           // 409600
#define BCP  (BB*CP)           // 1638400
#define NBCP (NN*BCP)          // 4915200
#define GATESC (2*CC)          // 512

// ---------------- scratch (static device globals; no runtime alloc) ----------------
__device__ float g_nodes [NBCP];
__device__ float g_th    [NBCP];
__device__ float g_sum   [NN*BCP];                 // 3 unordered pair sums
__device__ float g_scores[(size_t)EE*BB*PP*PP];    // 61.44M floats (scores -> atn in place)
__device__ float g_msg   [(size_t)EE*BCP];
__device__ float g_agg   [NBCP];
__device__ float g_gates [(size_t)NBB*GATESC*PP];
__device__ float g_rh    [NBCP];
__device__ float g_cand  [NBCP];
__device__ float g_wt_gates[9*512*512];            // [s][ci][oc]
__device__ float g_wt_cand [9*512*256];

// edge tables: permutations(3,2) = (0,1)(0,2)(1,0)(1,2)(2,0)(2,1)
__device__ __constant__ int c_recv[EE] = {0,0,1,1,2,2};
__device__ __constant__ int c_send[EE] = {1,2,0,2,0,1};
__device__ __constant__ int c_pair[EE] = {0,1,0,2,1,2};   // unordered pair id per edge
__device__ __constant__ int c_p0[NN]   = {0,0,1};         // pair -> (i,j)
__device__ __constant__ int c_p1[NN]   = {1,2,2};

// ---------------- GEMM tiling ----------------
#define BM 128
#define BN 128
#define BK 8
#define LDT 132   // padded smem row (128+4): conflict-free, keeps 16B alignment

__device__ __forceinline__ void mm_tile(const float (*As)[LDT], const float (*Bs)[LDT],
                                        float acc[8][8], int tx, int ty) {
#pragma unroll
    for (int kk = 0; kk < BK; kk++) {
        float4 a0 = *(const float4*)(&As[kk][ty*8]);
        float4 a1 = *(const float4*)(&As[kk][ty*8+4]);
        float4 b0 = *(const float4*)(&Bs[kk][tx*8]);
        float4 b1 = *(const float4*)(&Bs[kk][tx*8+4]);
        float a[8] = {a0.x,a0.y,a0.z,a0.w,a1.x,a1.y,a1.z,a1.w};
        float b[8] = {b0.x,b0.y,b0.z,b0.w,b1.x,b1.y,b1.z,b1.w};
#pragma unroll
        for (int i = 0; i < 8; i++)
#pragma unroll
            for (int j = 0; j < 8; j++)
                acc[i][j] += a[i]*b[j];
    }
}

// ============ theta: th[z][o][p] = sum_c W[o][c]*nodes[z][c][p] + bias[o] ============
// grid (13, 2, 12)
__global__ __launch_bounds__(256) void theta_gemm(const float* __restrict__ W,
                                                  const float* __restrict__ bias) {
    const int z = blockIdx.z;
    const float* Bp = g_nodes + (size_t)z*CP;
    float* Cp = g_th + (size_t)z*CP;
    const int m0 = blockIdx.y*BM, n0 = blockIdx.x*BN;
    __shared__ alignas(16) float As[BK][LDT];
    __shared__ alignas(16) float Bs[BK][LDT];
    const int tid = threadIdx.x, tx = tid & 15, ty = tid >> 4;
    float acc[8][8] = {};
    for (int k0 = 0; k0 < CC; k0 += BK) {
#pragma unroll
        for (int l = 0; l < 4; l++) {   // A: row-major [256][256]
            int idx = tid + l*256; int k = idx & 7, m = idx >> 3;
            As[k][m] = W[(size_t)(m0+m)*CC + k0 + k];
        }
#pragma unroll
        for (int l = 0; l < 4; l++) {   // B: [256][1600]
            int idx = tid + l*256; int n = idx & 127, k = idx >> 7;
            int gn = n0 + n;
            Bs[k][n] = (gn < PP) ? Bp[(size_t)(k0+k)*PP + gn] : 0.f;
        }
        __syncthreads();
        mm_tile(As, Bs, acc, tx, ty);
        __syncthreads();
    }
#pragma unroll
    for (int i = 0; i < 8; i++) {
        int m = m0 + ty*8 + i; float bv = bias[m];
#pragma unroll
        for (int j = 0; j < 8; j++) {
            int n = n0 + tx*8 + j;
            if (n < PP) Cp[(size_t)m*PP + n] = acc[i][j] + bv;
        }
    }
}

// ============ scores: S[z][p][q] = sum_c th[recv][c][p]*nodes[send][c][q] ============
// grid (13, 13, 24)
__global__ __launch_bounds__(256) void scores_gemm() {
    const int z = blockIdx.z, e = z >> 2, b = z & 3;
    const float* Ap = g_th    + (size_t)(c_recv[e]*BB + b)*CP;   // K-major [256][1600]
    const float* Bp = g_nodes + (size_t)(c_send[e]*BB + b)*CP;   // K-major [256][1600]
    float* Cp = g_scores + (size_t)z*PP*PP;
    const int m0 = blockIdx.y*BM, n0 = blockIdx.x*BN;
    __shared__ alignas(16) float As[BK][LDT];
    __shared__ alignas(16) float Bs[BK][LDT];
    const int tid = threadIdx.x, tx = tid & 15, ty = tid >> 4;
    float acc[8][8] = {};
    for (int k0 = 0; k0 < CC; k0 += BK) {
#pragma unroll
        for (int l = 0; l < 4; l++) {
            int idx = tid + l*256; int m = idx & 127, k = idx >> 7;
            int gm = m0 + m;
            As[k][m] = (gm < PP) ? Ap[(size_t)(k0+k)*PP + gm] : 0.f;
        }
#pragma unroll
        for (int l = 0; l < 4; l++) {
            int idx = tid + l*256; int n = idx & 127, k = idx >> 7;
            int gn = n0 + n;
            Bs[k][n] = (gn < PP) ? Bp[(size_t)(k0+k)*PP + gn] : 0.f;
        }
        __syncthreads();
        mm_tile(As, Bs, acc, tx, ty);
        __syncthreads();
    }
#pragma unroll
    for (int i = 0; i < 8; i++) {
        int m = m0 + ty*8 + i;
        if (m >= PP) continue;
#pragma unroll
        for (int j = 0; j < 8; j++) {
            int n = n0 + tx*8 + j;
            if (n < PP) Cp[(size_t)m*PP + n] = acc[i][j];
        }
    }
}

// ============ msg: M[z][c][p] = sum_q sum_pair[c][q] * atn[z][p][q] ============
// grid (13, 2, 24)
__global__ __launch_bounds__(256) void msg_gemm() {
    const int z = blockIdx.z, e = z >> 2, b = z & 3;
    const float* Ap = g_sum    + (size_t)(c_pair[e]*BB + b)*CP;  // row-major [256][1600]
    const float* Bp = g_scores + (size_t)z*PP*PP;                // atn [1600][1600], use B^T
    float* Cp = g_msg + (size_t)z*CP;
    const int m0 = blockIdx.y*BM, n0 = blockIdx.x*BN;
    __shared__ alignas(16) float As[BK][LDT];
    __shared__ alignas(16) float Bs[BK][LDT];
    const int tid = threadIdx.x, tx = tid & 15, ty = tid >> 4;
    float acc[8][8] = {};
    for (int k0 = 0; k0 < PP; k0 += BK) {
#pragma unroll
        for (int l = 0; l < 4; l++) {      // A[m][k], m<256 always in-range
            int idx = tid + l*256; int k = idx & 7, m = idx >> 3;
            As[k][m] = Ap[(size_t)(m0+m)*PP + k0 + k];
        }
#pragma unroll
        for (int l = 0; l < 4; l++) {      // B^T: Bs[k][n] = atn[n][k]
            int idx = tid + l*256; int k = idx & 7, n = idx >> 3;
            int gn = n0 + n;
            Bs[k][n] = (gn < PP) ? Bp[(size_t)gn*PP + k0 + k] : 0.f;
        }
        __syncthreads();
        mm_tile(As, Bs, acc, tx, ty);
        __syncthreads();
    }
#pragma unroll
    for (int i = 0; i < 8; i++) {
        int m = m0 + ty*8 + i;
#pragma unroll
        for (int j = 0; j < 8; j++) {
            int n = n0 + tx*8 + j;
            if (n < PP) Cp[(size_t)m*PP + n] = acc[i][j];
        }
    }
}

// ============ conv3x3 as 9 shifted GEMMs (implicit im2col) ============
// wt layout [s][ci(512)][oc], inputs: ci<256 -> inA, else inB
// grid (13, OC/128, 12)
__global__ __launch_bounds__(256) void conv_gemm(const float* __restrict__ wt,
                                                 const float* __restrict__ bias,
                                                 const float* __restrict__ inA,
                                                 const float* __restrict__ inB,
                                                 float* __restrict__ out, int OC) {
    const int z = blockIdx.z;
    const float* pA = inA + (size_t)z*CP;
    const float* pB = inB + (size_t)z*CP;
    float* pO = out + (size_t)z*OC*PP;
    const int m0 = blockIdx.y*BM, n0 = blockIdx.x*BN;
    __shared__ alignas(16) float As[BK][LDT];
    __shared__ alignas(16) float Bs[BK][LDT];
    const int tid = threadIdx.x, tx = tid & 15, ty = tid >> 4;
    const int nloc = tid & 127;
    const int gn = n0 + nloc;
    const int y = gn / WW, x = gn % WW;
    const bool npix = (gn < PP);
    float acc[8][8] = {};
    for (int s = 0; s < 9; s++) {
        const int ky = s/3 - 1, kx = s%3 - 1;
        const int yy = y + ky, xx = x + kx;
        const bool valid = npix && yy >= 0 && yy < HH && xx >= 0 && xx < WW;
        const int off = yy*WW + xx;
        const float* wts = wt + (size_t)s*512*OC;
        for (int k0 = 0; k0 < 512; k0 += BK) {
            const float* src = (k0 < 256) ? pA : (pB - 256*PP);
#pragma unroll
            for (int l = 0; l < 4; l++) {     // weights, coalesced in oc
                int idx = tid + l*256; int m = idx & 127, k = idx >> 7;
                As[k][m] = wts[(size_t)(k0+k)*OC + m0 + m];
            }
#pragma unroll
            for (int l = 0; l < 4; l++) {     // shifted activations
                int k = (tid >> 7) + 2*l;
                Bs[k][nloc] = valid ? src[(size_t)(k0+k)*PP + off] : 0.f;
            }
            __syncthreads();
            mm_tile(As, Bs, acc, tx, ty);
            __syncthreads();
        }
    }
#pragma unroll
    for (int i = 0; i < 8; i++) {
        int m = m0 + ty*8 + i; float bv = bias[m];
#pragma unroll
        for (int j = 0; j < 8; j++) {
            int n = n0 + tx*8 + j;
            if (n < PP) pO[(size_t)m*PP + n] = acc[i][j] + bv;
        }
    }
}

// ============ softmax over last dim (rows of 1600), in place on g_scores ============
__device__ __forceinline__ float block_reduce(float v, bool is_max) {
    __shared__ float s[32];
    __syncthreads();
#pragma unroll
    for (int o = 16; o > 0; o >>= 1) {
        float t = __shfl_xor_sync(0xffffffffu, v, o);
        v = is_max ? fmaxf(v, t) : (v + t);
    }
    const int w = threadIdx.x >> 5, l = threadIdx.x & 31;
    if (l == 0) s[w] = v;
    __syncthreads();
    if (w == 0) {
        v = (l < 8) ? s[l] : (is_max ? -INFINITY : 0.f);
#pragma unroll
        for (int o = 4; o > 0; o >>= 1) {
            float t = __shfl_xor_sync(0xffffffffu, v, o);
            v = is_max ? fmaxf(v, t) : (v + t);
        }
        if (l == 0) s[0] = v;
    }
    __syncthreads();
    return s[0];
}

__global__ __launch_bounds__(256) void softmax_rows() {
    float* row = g_scores + (size_t)blockIdx.x * PP;
    const int t = threadIdx.x;
    float v[7];
    float mx = -INFINITY;
#pragma unroll
    for (int i = 0; i < 7; i++) {
        int idx = t + i*256;
        v[i] = (idx < PP) ? row[idx] : -INFINITY;
        mx = fmaxf(mx, v[i]);
    }
    mx = block_reduce(mx, true);
    float sum = 0.f;
#pragma unroll
    for (int i = 0; i < 7; i++) {
        int idx = t + i*256;
        if (idx < PP) { v[i] = expf(v[i] - mx); sum += v[i]; }
    }
    sum = block_reduce(sum, false);
    const float inv = 1.f / sum;
#pragma unroll
    for (int i = 0; i < 7; i++) {
        int idx = t + i*256;
        if (idx < PP) row[idx] = v[i] * inv;
    }
}

// ============ elementwise kernels ============
__global__ __launch_bounds__(256) void sums_kernel() {      // unordered pair sums
    size_t i = (size_t)blockIdx.x*256 + threadIdx.x;
    if (i >= (size_t)NN*BCP) return;
    int p = (int)(i / BCP); size_t r = i % BCP;
    g_sum[i] = g_nodes[(size_t)c_p0[p]*BCP + r] + g_nodes[(size_t)c_p1[p]*BCP + r];
}

__global__ __launch_bounds__(256) void agg_kernel() {       // segment_sum (2 edges per node)
    size_t i = (size_t)blockIdx.x*256 + threadIdx.x;
    if (i >= (size_t)NBCP) return;
    int n = (int)(i / BCP); size_t r = i % BCP;
    g_agg[i] = g_msg[(size_t)(2*n)*BCP + r] + g_msg[(size_t)(2*n+1)*BCP + r];
}

__global__ __launch_bounds__(256) void rh_kernel() {        // r = sigmoid(gates[:,:256]); rh = r*h
    size_t i = (size_t)blockIdx.x*256 + threadIdx.x;
    if (i >= (size_t)NBCP) return;
    size_t nb = i / CP, cp = i % CP;
    float g = g_gates[nb*(size_t)(GATESC*PP) + cp];
    float r = 1.f / (1.f + expf(-g));
    g_rh[i] = r * g_nodes[i];
}

__global__ __launch_bounds__(256) void update_kernel() {    // h' = (1-z)h + z*tanh(cand)
    size_t i = (size_t)blockIdx.x*256 + threadIdx.x;
    if (i >= (size_t)NBCP) return;
    size_t nb = i / CP, cp = i % CP;
    float gz = g_gates[nb*(size_t)(GATESC*PP) + (size_t)CC*PP + cp];
    float zv = 1.f / (1.f + expf(-gz));
    float h = g_nodes[i];
    float cd = tanhf(g_cand[i]);
    g_nodes[i] = (1.f - zv)*h + zv*cd;
}

// weight transpose: w[oc][ci][3][3] -> wt[s][ci][oc]
__global__ __launch_bounds__(256) void transpose_w(const float* __restrict__ w,
                                                   float* __restrict__ wt, int OC) {
    size_t i = (size_t)blockIdx.x*256 + threadIdx.x;
    size_t total = (size_t)9*512*OC;
    if (i >= total) return;
    int s  = (int)(i / ((size_t)512*OC));
    int ci = (int)((i / OC) % 512);
    int oc = (int)(i % OC);
    wt[i] = w[((size_t)oc*512 + ci)*9 + s];
}

__global__ __launch_bounds__(256) void copy_in(const float* __restrict__ src) {
    size_t i = (size_t)blockIdx.x*256 + threadIdx.x;
    if (i < (size_t)NBCP/4) ((float4*)g_nodes)[i] = ((const float4*)src)[i];
}
__global__ __launch_bounds__(256) void copy_out(float* __restrict__ dst) {
    size_t i = (size_t)blockIdx.x*256 + threadIdx.x;
    if (i < (size_t)NBCP/4) ((float4*)dst)[i] = ((const float4*)g_nodes)[i];
}

// ---------------- host launch ----------------
extern "C" void kernel_launch(void* const* d_in, const int* in_sizes, int n_in,
                              void* d_out, int out_size) {
    const float* in_nodes = (const float*)d_in[0];
    const float* theta_w  = (const float*)d_in[1];
    const float* theta_b  = (const float*)d_in[2];
    const float* gw       = (const float*)d_in[3];
    const float* gb       = (const float*)d_in[4];
    const float* cw       = (const float*)d_in[5];
    const float* cb       = (const float*)d_in[6];
    float* out = (float*)d_out;

    float *p_agg, *p_nodes, *p_rh, *p_gates, *p_cand, *p_wtg, *p_wtc;
    cudaGetSymbolAddress((void**)&p_agg,   g_agg);
    cudaGetSymbolAddress((void**)&p_nodes, g_nodes);
    cudaGetSymbolAddress((void**)&p_rh,    g_rh);
    cudaGetSymbolAddress((void**)&p_gates, g_gates);
    cudaGetSymbolAddress((void**)&p_cand,  g_cand);
    cudaGetSymbolAddress((void**)&p_wtg,   g_wt_gates);
    cudaGetSymbolAddress((void**)&p_wtc,   g_wt_cand);

    copy_in<<<(NBCP/4 + 255)/256, 256>>>(in_nodes);
    transpose_w<<<((size_t)9*512*512 + 255)/256, 256>>>(gw, p_wtg, 512);
    transpose_w<<<((size_t)9*512*256 + 255)/256, 256>>>(cw, p_wtc, 256);

    const int EW = NBCP/256;  // 19200 blocks for NBCP-sized elementwise
    for (int pass = 0; pass < 2; pass++) {
        theta_gemm <<<dim3(13, 2, NBB), 256>>>(theta_w, theta_b);
        sums_kernel<<<EW, 256>>>();
        scores_gemm<<<dim3(13, 13, EE*BB), 256>>>();
        softmax_rows<<<EE*BB*PP, 256>>>();
        msg_gemm   <<<dim3(13, 2, EE*BB), 256>>>();
        agg_kernel <<<EW, 256>>>();
        conv_gemm  <<<dim3(13, 4, NBB), 256>>>(p_wtg, gb, p_agg, p_nodes, p_gates, 512);
        rh_kernel  <<<EW, 256>>>();
        conv_gemm  <<<dim3(13, 2, NBB), 256>>>(p_wtc, cb, p_agg, p_rh, p_cand, 256);
        update_kernel<<<EW, 256>>>();
    }
    copy_out<<<(NBCP/4 + 255)/256, 256>>>(out);
}

// round 2
// speedup vs baseline: 1.3358x; 1.3358x over previous
#include <cuda_runtime.h>
#include <cuda_bf16.h>
#include <math.h>

// ---------------- problem constants ----------------
#define NN   3
#define BB   4
#define CC   256
#define HH   40
#define WW   40
#define PP   (HH*WW)           // 1600
#define EE   6
#define NBB  (NN*BB)           // 12
#define CP   (CC*PP)           // 409600
#define BCP  (BB*CP)
#define NBCP (NN*BCP)
#define GATESC (2*CC)

// ---------------- scratch ----------------
__device__ float g_nodes [NBCP];
__device__ float g_th    [NBCP];
__device__ float g_sum   [NN*BCP];
__device__ float g_scores[(size_t)EE*BB*PP*PP];
__device__ float g_msg   [(size_t)EE*BCP];
__device__ float g_agg   [NBCP];
__device__ float g_gates [(size_t)NBB*GATESC*PP];
__device__ float g_rh    [NBCP];
__device__ float g_cand  [NBCP];
__device__ float g_wt_gates[9*512*512];
__device__ float g_wt_cand [9*512*256];

__device__ __constant__ int c_recv[EE] = {0,0,1,1,2,2};
__device__ __constant__ int c_send[EE] = {1,2,0,2,0,1};
__device__ __constant__ int c_pair[EE] = {0,1,0,2,1,2};
__device__ __constant__ int c_p0[NN]   = {0,0,1};
__device__ __constant__ int c_p1[NN]   = {1,2,2};

// ---------------- GEMM tiling ----------------
#define BM 128
#define BN 128
#define BK 16
#define LDT 132

__device__ __forceinline__ void compute16(const float (*As)[LDT], const float (*Bs)[LDT],
                                          float acc[8][8], int tx, int ty) {
#pragma unroll
    for (int kk = 0; kk < BK; kk++) {
        float4 a0 = *(const float4*)(&As[kk][ty*4]);
        float4 a1 = *(const float4*)(&As[kk][64 + ty*4]);
        float4 b0 = *(const float4*)(&Bs[kk][tx*4]);
        float4 b1 = *(const float4*)(&Bs[kk][64 + tx*4]);
        float a[8] = {a0.x,a0.y,a0.z,a0.w,a1.x,a1.y,a1.z,a1.w};
        float b[8] = {b0.x,b0.y,b0.z,b0.w,b1.x,b1.y,b1.z,b1.w};
#pragma unroll
        for (int i = 0; i < 8; i++)
#pragma unroll
            for (int j = 0; j < 8; j++)
                acc[i][j] += a[i]*b[j];
    }
}
__device__ __forceinline__ int mmap8(int ty, int i) { return (i<4) ? ty*4+i : 64+ty*4+(i-4); }

// ============ theta: th[z][o][p] = sum_c W[o][c]*nodes[z][c][p] + bias[o] ============
__global__ __launch_bounds__(256) void theta_gemm(const float* __restrict__ W,
                                                  const float* __restrict__ bias) {
    const int z = blockIdx.z;
    const float* Bp = g_nodes + (size_t)z*CP;
    float* Cp = g_th + (size_t)z*CP;
    const int m0 = blockIdx.y*BM, n0 = blockIdx.x*BN;
    __shared__ alignas(16) float As[2][BK][LDT];
    __shared__ alignas(16) float Bs[2][BK][LDT];
    const int tid = threadIdx.x, tx = tid & 15, ty = tid >> 4;
    const int am = tid >> 1, ak = (tid & 1)*8;       // A: 8 consecutive k
    const int bn4 = tid & 31, bk = tid >> 5;          // B: float4 along n, rows bk,bk+8
    const bool nfull = (n0 + BN) <= PP;
    float acc[8][8] = {};
    float ra[8], rb[8];
    const int NT = CC/BK;

    auto loadA = [&](int t) {
        const float* p = W + (size_t)(m0+am)*CC + t*BK + ak;
        float4 v0 = *(const float4*)p, v1 = *(const float4*)(p+4);
        ra[0]=v0.x; ra[1]=v0.y; ra[2]=v0.z; ra[3]=v0.w;
        ra[4]=v1.x; ra[5]=v1.y; ra[6]=v1.z; ra[7]=v1.w;
    };
    auto loadB = [&](int t) {
        const float* p = Bp + (size_t)(t*BK + bk)*PP + n0 + bn4*4;
        if (nfull) {
            float4 v0 = *(const float4*)p, v1 = *(const float4*)(p + 8*PP);
            rb[0]=v0.x; rb[1]=v0.y; rb[2]=v0.z; rb[3]=v0.w;
            rb[4]=v1.x; rb[5]=v1.y; rb[6]=v1.z; rb[7]=v1.w;
        } else {
            int gb = n0 + bn4*4;
#pragma unroll
            for (int e = 0; e < 4; e++) {
                rb[e]   = (gb+e < PP) ? p[e]        : 0.f;
                rb[e+4] = (gb+e < PP) ? p[8*PP + e] : 0.f;
            }
        }
    };
    auto store = [&](int buf) {
#pragma unroll
        for (int j = 0; j < 8; j++) As[buf][ak+j][am] = ra[j];
        *(float4*)&Bs[buf][bk][bn4*4]   = make_float4(rb[0],rb[1],rb[2],rb[3]);
        *(float4*)&Bs[buf][bk+8][bn4*4] = make_float4(rb[4],rb[5],rb[6],rb[7]);
    };

    loadA(0); loadB(0); store(0); __syncthreads();
    for (int t = 1; t < NT; t++) {
        loadA(t); loadB(t);
        compute16(As[(t-1)&1], Bs[(t-1)&1], acc, tx, ty);
        store(t&1);
        __syncthreads();
    }
    compute16(As[(NT-1)&1], Bs[(NT-1)&1], acc, tx, ty);

#pragma unroll
    for (int i = 0; i < 8; i++) {
        int m = m0 + mmap8(ty, i); float bv = bias[m];
#pragma unroll
        for (int j = 0; j < 8; j++) {
            int n = n0 + mmap8(tx, j);
            if (n < PP) Cp[(size_t)m*PP + n] = acc[i][j] + bv;
        }
    }
}

// ============ scores: S[z][p][q] = sum_c th[recv][c][p]*nodes[send][c][q] ============
__global__ __launch_bounds__(256) void scores_gemm() {
    const int z = blockIdx.z, e = z >> 2, b = z & 3;
    const float* Ap = g_th    + (size_t)(c_recv[e]*BB + b)*CP;
    const float* Bp = g_nodes + (size_t)(c_send[e]*BB + b)*CP;
    float* Cp = g_scores + (size_t)z*PP*PP;
    const int m0 = blockIdx.y*BM, n0 = blockIdx.x*BN;
    __shared__ alignas(16) float As[2][BK][LDT];
    __shared__ alignas(16) float Bs[2][BK][LDT];
    const int tid = threadIdx.x, tx = tid & 15, ty = tid >> 4;
    const int v4 = tid & 31, vk = tid >> 5;
    const bool mfull = (m0 + BM) <= PP;
    const bool nfull = (n0 + BN) <= PP;
    float acc[8][8] = {};
    float ra[8], rb[8];
    const int NT = CC/BK;

    auto loadA = [&](int t) {
        const float* p = Ap + (size_t)(t*BK + vk)*PP + m0 + v4*4;
        if (mfull) {
            float4 a0 = *(const float4*)p, a1 = *(const float4*)(p + 8*PP);
            ra[0]=a0.x; ra[1]=a0.y; ra[2]=a0.z; ra[3]=a0.w;
            ra[4]=a1.x; ra[5]=a1.y; ra[6]=a1.z; ra[7]=a1.w;
        } else {
            int gm = m0 + v4*4;
#pragma unroll
            for (int e2 = 0; e2 < 4; e2++) {
                ra[e2]   = (gm+e2 < PP) ? p[e2]        : 0.f;
                ra[e2+4] = (gm+e2 < PP) ? p[8*PP + e2] : 0.f;
            }
        }
    };
    auto loadB = [&](int t) {
        const float* p = Bp + (size_t)(t*BK + vk)*PP + n0 + v4*4;
        if (nfull) {
            float4 b0 = *(const float4*)p, b1 = *(const float4*)(p + 8*PP);
            rb[0]=b0.x; rb[1]=b0.y; rb[2]=b0.z; rb[3]=b0.w;
            rb[4]=b1.x; rb[5]=b1.y; rb[6]=b1.z; rb[7]=b1.w;
        } else {
            int gn = n0 + v4*4;
#pragma unroll
            for (int e2 = 0; e2 < 4; e2++) {
                rb[e2]   = (gn+e2 < PP) ? p[e2]        : 0.f;
                rb[e2+4] = (gn+e2 < PP) ? p[8*PP + e2] : 0.f;
            }
        }
    };
    auto store = [&](int buf) {
        *(float4*)&As[buf][vk][v4*4]   = make_float4(ra[0],ra[1],ra[2],ra[3]);
        *(float4*)&As[buf][vk+8][v4*4] = make_float4(ra[4],ra[5],ra[6],ra[7]);
        *(float4*)&Bs[buf][vk][v4*4]   = make_float4(rb[0],rb[1],rb[2],rb[3]);
        *(float4*)&Bs[buf][vk+8][v4*4] = make_float4(rb[4],rb[5],rb[6],rb[7]);
    };

    loadA(0); loadB(0); store(0); __syncthreads();
    for (int t = 1; t < NT; t++) {
        loadA(t); loadB(t);
        compute16(As[(t-1)&1], Bs[(t-1)&1], acc, tx, ty);
        store(t&1);
        __syncthreads();
    }
    compute16(As[(NT-1)&1], Bs[(NT-1)&1], acc, tx, ty);

#pragma unroll
    for (int i = 0; i < 8; i++) {
        int m = m0 + mmap8(ty, i);
        if (m >= PP) continue;
#pragma unroll
        for (int j = 0; j < 8; j++) {
            int n = n0 + mmap8(tx, j);
            if (n < PP) Cp[(size_t)m*PP + n] = acc[i][j];
        }
    }
}

// ============ msg: M[z][c][p] = sum_q sum_pair[c][q] * atn[z][p][q] ============
__global__ __launch_bounds__(256) void msg_gemm() {
    const int z = blockIdx.z, e = z >> 2, b = z & 3;
    const float* Ap = g_sum    + (size_t)(c_pair[e]*BB + b)*CP;   // [256][1600] row-major
    const float* Bp = g_scores + (size_t)z*PP*PP;                 // atn, used transposed
    float* Cp = g_msg + (size_t)z*CP;
    const int m0 = blockIdx.y*BM, n0 = blockIdx.x*BN;
    __shared__ alignas(16) float As[2][BK][LDT];
    __shared__ alignas(16) float Bs[2][BK][LDT];
    const int tid = threadIdx.x, tx = tid & 15, ty = tid >> 4;
    const int r  = tid >> 1, kh = (tid & 1)*8;    // row (m or n), 8 consecutive k
    const int gn = n0 + r;
    const bool nok = (gn < PP);
    float acc[8][8] = {};
    float ra[8], rb[8];
    const int NT = PP/BK;   // 100

    auto loadA = [&](int t) {
        const float* p = Ap + (size_t)(m0+r)*PP + t*BK + kh;
        float4 v0 = *(const float4*)p, v1 = *(const float4*)(p+4);
        ra[0]=v0.x; ra[1]=v0.y; ra[2]=v0.z; ra[3]=v0.w;
        ra[4]=v1.x; ra[5]=v1.y; ra[6]=v1.z; ra[7]=v1.w;
    };
    auto loadB = [&](int t) {
        if (nok) {
            const float* p = Bp + (size_t)gn*PP + t*BK + kh;
            float4 v0 = *(const float4*)p, v1 = *(const float4*)(p+4);
            rb[0]=v0.x; rb[1]=v0.y; rb[2]=v0.z; rb[3]=v0.w;
            rb[4]=v1.x; rb[5]=v1.y; rb[6]=v1.z; rb[7]=v1.w;
        } else {
#pragma unroll
            for (int j = 0; j < 8; j++) rb[j] = 0.f;
        }
    };
    auto store = [&](int buf) {
#pragma unroll
        for (int j = 0; j < 8; j++) As[buf][kh+j][r] = ra[j];
#pragma unroll
        for (int j = 0; j < 8; j++) Bs[buf][kh+j][r] = rb[j];
    };

    loadA(0); loadB(0); store(0); __syncthreads();
    for (int t = 1; t < NT; t++) {
        loadA(t); loadB(t);
        compute16(As[(t-1)&1], Bs[(t-1)&1], acc, tx, ty);
        store(t&1);
        __syncthreads();
    }
    compute16(As[(NT-1)&1], Bs[(NT-1)&1], acc, tx, ty);

#pragma unroll
    for (int i = 0; i < 8; i++) {
        int m = m0 + mmap8(ty, i);
#pragma unroll
        for (int j = 0; j < 8; j++) {
            int n = n0 + mmap8(tx, j);
            if (n < PP) Cp[(size_t)m*PP + n] = acc[i][j];
        }
    }
}

// ============ conv3x3 as 9 shifted GEMMs ============
__global__ __launch_bounds__(256) void conv_gemm(const float* __restrict__ wt,
                                                 const float* __restrict__ bias,
                                                 const float* __restrict__ inA,
                                                 const float* __restrict__ inB,
                                                 float* __restrict__ out, int OC) {
    const int z = blockIdx.z;
    const float* pA = inA + (size_t)z*CP;
    const float* pBx = inB + (size_t)z*CP - (size_t)256*PP;  // indexed by k in [256,512)
    float* pO = out + (size_t)z*OC*PP;
    const int m0 = blockIdx.y*BM, n0 = blockIdx.x*BN;
    __shared__ alignas(16) float As[2][BK][LDT];
    __shared__ alignas(16) float Bs[2][BK][LDT];
    const int tid = threadIdx.x, tx = tid & 15, ty = tid >> 4;
    const int a4 = tid & 31, ak = tid >> 5;
    const int nloc = tid & 127, kb8 = (tid >> 7)*8;
    const int gn = n0 + nloc;
    const int y = gn / WW, x = gn % WW;
    const bool npix = (gn < PP);
    float acc[8][8] = {};
    float ra[8], rb[8];
    const int KB = 512/BK;        // 32 per shift
    const int NT = 9*KB;          // 288

    auto loadA = [&](int t) {
        int s = t >> 5, k0 = (t & 31)*BK;
        const float* p = wt + (size_t)s*512*OC + (size_t)(k0+ak)*OC + m0 + a4*4;
        float4 v0 = *(const float4*)p, v1 = *(const float4*)(p + (size_t)8*OC);
        ra[0]=v0.x; ra[1]=v0.y; ra[2]=v0.z; ra[3]=v0.w;
        ra[4]=v1.x; ra[5]=v1.y; ra[6]=v1.z; ra[7]=v1.w;
    };
    auto loadB = [&](int t) {
        int s = t >> 5, k0 = (t & 31)*BK;
        int ky = s/3 - 1, kx = s%3 - 1;
        int yy = y + ky, xx = x + kx;
        bool valid = npix && yy >= 0 && yy < HH && xx >= 0 && xx < WW;
        int off = yy*WW + xx;
        const float* src = (k0 < 256) ? pA : pBx;
        if (valid) {
#pragma unroll
            for (int l = 0; l < 8; l++)
                rb[l] = src[(size_t)(k0 + kb8 + l)*PP + off];
        } else {
#pragma unroll
            for (int l = 0; l < 8; l++) rb[l] = 0.f;
        }
    };
    auto store = [&](int buf) {
        *(float4*)&As[buf][ak][a4*4]   = make_float4(ra[0],ra[1],ra[2],ra[3]);
        *(float4*)&As[buf][ak+8][a4*4] = make_float4(ra[4],ra[5],ra[6],ra[7]);
#pragma unroll
        for (int l = 0; l < 8; l++) Bs[buf][kb8+l][nloc] = rb[l];
    };

    loadA(0); loadB(0); store(0); __syncthreads();
    for (int t = 1; t < NT; t++) {
        loadA(t); loadB(t);
        compute16(As[(t-1)&1], Bs[(t-1)&1], acc, tx, ty);
        store(t&1);
        __syncthreads();
    }
    compute16(As[(NT-1)&1], Bs[(NT-1)&1], acc, tx, ty);

#pragma unroll
    for (int i = 0; i < 8; i++) {
        int m = m0 + mmap8(ty, i); float bv = bias[m];
#pragma unroll
        for (int j = 0; j < 8; j++) {
            int n = n0 + mmap8(tx, j);
            if (n < PP) pO[(size_t)m*PP + n] = acc[i][j] + bv;
        }
    }
}

// ============ softmax over last dim, in place ============
__device__ __forceinline__ float block_reduce(float v, bool is_max) {
    __shared__ float s[32];
    __syncthreads();
#pragma unroll
    for (int o = 16; o > 0; o >>= 1) {
        float t = __shfl_xor_sync(0xffffffffu, v, o);
        v = is_max ? fmaxf(v, t) : (v + t);
    }
    const int w = threadIdx.x >> 5, l = threadIdx.x & 31;
    if (l == 0) s[w] = v;
    __syncthreads();
    if (w == 0) {
        v = (l < 8) ? s[l] : (is_max ? -INFINITY : 0.f);
#pragma unroll
        for (int o = 4; o > 0; o >>= 1) {
            float t = __shfl_xor_sync(0xffffffffu, v, o);
            v = is_max ? fmaxf(v, t) : (v + t);
        }
        if (l == 0) s[0] = v;
    }
    __syncthreads();
    return s[0];
}

__global__ __launch_bounds__(256) void softmax_rows() {
    float* row = g_scores + (size_t)blockIdx.x * PP;
    const int t = threadIdx.x;
    float v[7];
    float mx = -INFINITY;
#pragma unroll
    for (int i = 0; i < 7; i++) {
        int idx = t + i*256;
        v[i] = (idx < PP) ? row[idx] : -INFINITY;
        mx = fmaxf(mx, v[i]);
    }
    mx = block_reduce(mx, true);
    float sum = 0.f;
#pragma unroll
    for (int i = 0; i < 7; i++) {
        int idx = t + i*256;
        if (idx < PP) { v[i] = __expf(v[i] - mx); sum += v[i]; }
    }
    sum = block_reduce(sum, false);
    const float inv = 1.f / sum;
#pragma unroll
    for (int i = 0; i < 7; i++) {
        int idx = t + i*256;
        if (idx < PP) row[idx] = v[i] * inv;
    }
}

// ============ elementwise ============
__global__ __launch_bounds__(256) void sums_kernel() {
    size_t i = (size_t)blockIdx.x*256 + threadIdx.x;
    if (i >= (size_t)NN*BCP) return;
    int p = (int)(i / BCP); size_t r = i % BCP;
    g_sum[i] = g_nodes[(size_t)c_p0[p]*BCP + r] + g_nodes[(size_t)c_p1[p]*BCP + r];
}

__global__ __launch_bounds__(256) void agg_kernel() {
    size_t i = (size_t)blockIdx.x*256 + threadIdx.x;
    if (i >= (size_t)NBCP) return;
    int n = (int)(i / BCP); size_t r = i % BCP;
    g_agg[i] = g_msg[(size_t)(2*n)*BCP + r] + g_msg[(size_t)(2*n+1)*BCP + r];
}

__global__ __launch_bounds__(256) void rh_kernel() {
    size_t i = (size_t)blockIdx.x*256 + threadIdx.x;
    if (i >= (size_t)NBCP) return;
    size_t nb = i / CP, cp = i % CP;
    float g = g_gates[nb*(size_t)(GATESC*PP) + cp];
    float r = 1.f / (1.f + __expf(-g));
    g_rh[i] = r * g_nodes[i];
}

__global__ __launch_bounds__(256) void update_kernel() {
    size_t i = (size_t)blockIdx.x*256 + threadIdx.x;
    if (i >= (size_t)NBCP) return;
    size_t nb = i / CP, cp = i % CP;
    float gz = g_gates[nb*(size_t)(GATESC*PP) + (size_t)CC*PP + cp];
    float zv = 1.f / (1.f + __expf(-gz));
    float h = g_nodes[i];
    float cd = tanhf(g_cand[i]);
    g_nodes[i] = (1.f - zv)*h + zv*cd;
}

__global__ __launch_bounds__(256) void transpose_w(const float* __restrict__ w,
                                                   float* __restrict__ wt, int OC) {
    size_t i = (size_t)blockIdx.x*256 + threadIdx.x;
    size_t total = (size_t)9*512*OC;
    if (i >= total) return;
    int s  = (int)(i / ((size_t)512*OC));
    int ci = (int)((i / OC) % 512);
    int oc = (int)(i % OC);
    wt[i] = w[((size_t)oc*512 + ci)*9 + s];
}

__global__ __launch_bounds__(256) void copy_in(const float* __restrict__ src) {
    size_t i = (size_t)blockIdx.x*256 + threadIdx.x;
    if (i < (size_t)NBCP/4) ((float4*)g_nodes)[i] = ((const float4*)src)[i];
}
__global__ __launch_bounds__(256) void copy_out(float* __restrict__ dst) {
    size_t i = (size_t)blockIdx.x*256 + threadIdx.x;
    if (i < (size_t)NBCP/4) ((float4*)dst)[i] = ((const float4*)g_nodes)[i];
}

// ---------------- host launch ----------------
extern "C" void kernel_launch(void* const* d_in, const int* in_sizes, int n_in,
                              void* d_out, int out_size) {
    const float* in_nodes = (const float*)d_in[0];
    const float* theta_w  = (const float*)d_in[1];
    const float* theta_b  = (const float*)d_in[2];
    const float* gw       = (const float*)d_in[3];
    const float* gb       = (const float*)d_in[4];
    const float* cw       = (const float*)d_in[5];
    const float* cb       = (const float*)d_in[6];
    float* out = (float*)d_out;

    float *p_agg, *p_nodes, *p_rh, *p_gates, *p_cand, *p_wtg, *p_wtc;
    cudaGetSymbolAddress((void**)&p_agg,   g_agg);
    cudaGetSymbolAddress((void**)&p_nodes, g_nodes);
    cudaGetSymbolAddress((void**)&p_rh,    g_rh);
    cudaGetSymbolAddress((void**)&p_gates, g_gates);
    cudaGetSymbolAddress((void**)&p_cand,  g_cand);
    cudaGetSymbolAddress((void**)&p_wtg,   g_wt_gates);
    cudaGetSymbolAddress((void**)&p_wtc,   g_wt_cand);

    copy_in<<<(NBCP/4 + 255)/256, 256>>>(in_nodes);
    transpose_w<<<((size_t)9*512*512 + 255)/256, 256>>>(gw, p_wtg, 512);
    transpose_w<<<((size_t)9*512*256 + 255)/256, 256>>>(cw, p_wtc, 256);

    const int EW = NBCP/256;
    for (int pass = 0; pass < 2; pass++) {
        theta_gemm <<<dim3(13, 2, NBB), 256>>>(theta_w, theta_b);
        sums_kernel<<<EW, 256>>>();
        scores_gemm<<<dim3(13, 13, EE*BB), 256>>>();
        softmax_rows<<<EE*BB*PP, 256>>>();
        msg_gemm   <<<dim3(13, 2, EE*BB), 256>>>();
        agg_kernel <<<EW, 256>>>();
        conv_gemm  <<<dim3(13, 4, NBB), 256>>>(p_wtg, gb, p_agg, p_nodes, p_gates, 512);
        rh_kernel  <<<EW, 256>>>();
        conv_gemm  <<<dim3(13, 2, NBB), 256>>>(p_wtc, cb, p_agg, p_rh, p_cand, 256);
        update_kernel<<<EW, 256>>>();
    }
    copy_out<<<(NBCP/4 + 255)/256, 256>>>(out);
}

// round 5
// speedup vs baseline: 2.5298x; 1.8938x over previous
#include <cuda_runtime.h>
#include <cuda_bf16.h>
#include <math.h>
#include <stdint.h>

// ---------------- problem constants ----------------
#define NN   3
#define BB   4
#define CC   256
#define HH   40
#define WW   40
#define PP   (HH*WW)           // 1600
#define EE   6
#define NBB  (NN*BB)           // 12
#define CP   (CC*PP)           // 409600
#define BCP  (BB*CP)
#define NBCP (NN*BCP)          // 4915200

// ---------------- scratch ----------------
__device__ float g_nodes [NBCP];
__device__ float g_th    [NBCP];
__device__ float g_scores[(size_t)EE*BB*PP*PP];
__device__ float g_msg   [(size_t)EE*BCP];
__device__ float g_gates [(size_t)NBB*512*PP];
__device__ float g_cand  [NBCP];

// bf16 hi/lo split buffers (16B-aligned for cp.async)
__device__ __align__(16) __nv_bfloat16 g_atnH[(size_t)EE*BB*PP*PP];
__device__ __align__(16) __nv_bfloat16 g_atnL[(size_t)EE*BB*PP*PP];
__device__ __align__(16) __nv_bfloat16 g_nodesTH[NBCP], g_nodesTL[NBCP]; // [z][p][c]
__device__ __align__(16) __nv_bfloat16 g_thTH[NBCP],    g_thTL[NBCP];    // [z][p][c]
__device__ __align__(16) __nv_bfloat16 g_sumH[NN*BCP],  g_sumL[NN*BCP];  // [pair*b][c][q]
__device__ __align__(16) __nv_bfloat16 g_aggTH[NBCP],   g_aggTL[NBCP];   // [z][p][c]
__device__ __align__(16) __nv_bfloat16 g_rhTH[NBCP],    g_rhTL[NBCP];    // [z][p][c]
__device__ __align__(16) __nv_bfloat16 g_wgH[9*512*512], g_wgL[9*512*512]; // [s][oc][ci]
__device__ __align__(16) __nv_bfloat16 g_wcH[9*256*512], g_wcL[9*256*512];

__device__ __constant__ int c_recv[EE] = {0,0,1,1,2,2};
__device__ __constant__ int c_send[EE] = {1,2,0,2,0,1};
__device__ __constant__ int c_pair[EE] = {0,1,0,2,1,2};
__device__ __constant__ int c_p0[NN]   = {0,0,1};
__device__ __constant__ int c_p1[NN]   = {1,2,2};

// ================= low-level helpers (portable PTX only) =================
__device__ __forceinline__ uint32_t smem_u32(const void* p) {
    uint32_t a;
    asm("{ .reg .u64 t; cvta.to.shared.u64 t, %1; cvt.u32.u64 %0, t; }" : "=r"(a) : "l"(p));
    return a;
}
__device__ __forceinline__ void cp16(uint32_t dst, const void* src, bool v) {
    asm volatile("cp.async.cg.shared.global [%0], [%1], 16, %2;"
                 :: "r"(dst), "l"(src), "r"(v ? 16 : 0));
}
#define CP_COMMIT() asm volatile("cp.async.commit_group;" ::: "memory")
#define CP_WAIT0()  asm volatile("cp.async.wait_group 0;" ::: "memory")

__device__ __forceinline__ void ldsm4(uint32_t (&r)[4], uint32_t addr) {
    asm volatile("ldmatrix.sync.aligned.m8n8.x4.shared.b16 {%0,%1,%2,%3}, [%4];"
                 : "=r"(r[0]), "=r"(r[1]), "=r"(r[2]), "=r"(r[3]) : "r"(addr));
}
__device__ __forceinline__ void mma16816(float* c, const uint32_t (&a)[4],
                                         uint32_t b0, uint32_t b1) {
    asm volatile("mma.sync.aligned.m16n8k16.row.col.f32.bf16.bf16.f32 "
                 "{%0,%1,%2,%3}, {%4,%5,%6,%7}, {%8,%9}, {%0,%1,%2,%3};"
                 : "+f"(c[0]), "+f"(c[1]), "+f"(c[2]), "+f"(c[3])
                 : "r"(a[0]), "r"(a[1]), "r"(a[2]), "r"(a[3]), "r"(b0), "r"(b1));
}

// ---------------- tile geometry ----------------
#define TSTRIDE 40
#define TILE_B  (128*TSTRIDE*2)   // 10240 bytes per tile buffer

__device__ __forceinline__ void compute_chunk(uint32_t aT, uint32_t bT,
                                              int lane, int wm, int wn,
                                              float (*acc)[4][4]) {
    const int arow = wm*64 + ((lane>>3)&1)*8 + (lane&7);
    const int acol = (lane>>4)*8;
    const int brow = wn*32 + ((lane>>4)&1)*8 + (lane&7);
    const int bcol = ((lane>>3)&1)*8;
#pragma unroll
    for (int ks = 0; ks < 2; ks++) {
        uint32_t a[4][4], b[2][4];
#pragma unroll
        for (int mt = 0; mt < 4; mt++)
            ldsm4(a[mt], aT + (uint32_t)(((arow + mt*16)*TSTRIDE) + acol + ks*16)*2);
#pragma unroll
        for (int np = 0; np < 2; np++)
            ldsm4(b[np], bT + (uint32_t)(((brow + np*16)*TSTRIDE) + bcol + ks*16)*2);
#pragma unroll
        for (int mt = 0; mt < 4; mt++)
#pragma unroll
            for (int nt = 0; nt < 4; nt++)
                mma16816(acc[mt][nt], a[mt], b[nt>>1][(nt&1)*2], b[nt>>1][(nt&1)*2+1]);
    }
}

__device__ __forceinline__ void epilogue(float (*acc)[4][4], float* out,
                                         int m0, int n0, int Mtot, int Ntot,
                                         const float* bias, int lane, int wm, int wn) {
#pragma unroll
    for (int mt = 0; mt < 4; mt++) {
        int m = m0 + wm*64 + mt*16 + (lane>>2);
        float bv0 = (bias && m < Mtot) ? bias[m] : 0.f;
        float bv1 = (bias && m+8 < Mtot) ? bias[m+8] : 0.f;
#pragma unroll
        for (int nt = 0; nt < 4; nt++) {
            int n = n0 + wn*32 + nt*8 + (lane&3)*2;
            if (n >= Ntot) continue;
            if (m < Mtot) {
                float2 v = make_float2(acc[mt][nt][0] + bv0, acc[mt][nt][1] + bv0);
                *(float2*)&out[(size_t)m*Ntot + n] = v;
            }
            if (m+8 < Mtot) {
                float2 v = make_float2(acc[mt][nt][2] + bv1, acc[mt][nt][3] + bv1);
                *(float2*)&out[(size_t)(m+8)*Ntot + n] = v;
            }
        }
    }
}

// ============ scores: S[p][q] = sum_c th[p][c] * nodes[q][c], K'=768 ============
__global__ __launch_bounds__(256) void scores_mma() {
    __shared__ alignas(16) __nv_bfloat16 As[2][128][TSTRIDE];
    __shared__ alignas(16) __nv_bfloat16 Bs[2][128][TSTRIDE];
    const int tid = threadIdx.x, lane = tid & 31, wid = tid >> 5;
    const int wm = wid & 1, wn = wid >> 1;
    const int z = blockIdx.z, e = z >> 2, b = z & 3;
    const int zr = c_recv[e]*BB + b, zs = c_send[e]*BB + b;
    const int m0 = blockIdx.y*128, n0 = blockIdx.x*128;
    float* Cp = g_scores + (size_t)z*PP*PP;
    const uint32_t sA = smem_u32(As), sB = smem_u32(Bs);

    const int r0 = tid >> 2, seg16 = (tid & 3)*8;
    float acc[4][4][4] = {};

    auto stage = [&](int t, int buf) {
        int sg = t >> 3, k0 = (t & 7)*32 + seg16;
        const __nv_bfloat16* aS = (sg == 1) ? g_thTL : g_thTH;
        const __nv_bfloat16* bS = (sg == 2) ? g_nodesTL : g_nodesTH;
        uint32_t aT = sA + buf*TILE_B, bT = sB + buf*TILE_B;
#pragma unroll
        for (int i = 0; i < 2; i++) {
            int row = r0 + i*64;
            int gm = m0 + row, gn = n0 + row;
            bool va = gm < PP, vb = gn < PP;
            const __nv_bfloat16* pa = aS + ((size_t)zr*PP + (va ? gm : 0))*256 + k0;
            const __nv_bfloat16* pb = bS + ((size_t)zs*PP + (vb ? gn : 0))*256 + k0;
            uint32_t o = (uint32_t)(row*TSTRIDE + seg16)*2;
            cp16(aT + o, pa, va);
            cp16(bT + o, pb, vb);
        }
    };

    const int NT = 24;
    stage(0, 0); CP_COMMIT();
    for (int t = 0; t < NT; t++) {
        CP_WAIT0(); __syncthreads();
        if (t+1 < NT) { stage(t+1, (t+1)&1); CP_COMMIT(); }
        compute_chunk(sA + (t&1)*TILE_B, sB + (t&1)*TILE_B, lane, wm, wn, acc);
        __syncthreads();
    }
    epilogue(acc, Cp, m0, n0, PP, PP, nullptr, lane, wm, wn);
}

// ============ msg: M[c][p] = sum_q sum[c][q] * atn[p][q], K'=4800 ============
__global__ __launch_bounds__(256) void msg_mma() {
    __shared__ alignas(16) __nv_bfloat16 As[2][128][TSTRIDE];
    __shared__ alignas(16) __nv_bfloat16 Bs[2][128][TSTRIDE];
    const int tid = threadIdx.x, lane = tid & 31, wid = tid >> 5;
    const int wm = wid & 1, wn = wid >> 1;
    const int z = blockIdx.z, e = z >> 2, b = z & 3;
    const int zp = c_pair[e]*BB + b;
    const int m0 = blockIdx.y*128, n0 = blockIdx.x*128;
    float* Cp = g_msg + (size_t)z*CP;
    const uint32_t sA = smem_u32(As), sB = smem_u32(Bs);

    const int r0 = tid >> 2, seg16 = (tid & 3)*8;
    float acc[4][4][4] = {};

    auto stage = [&](int t, int buf) {
        int sg = t / 50, k0 = (t % 50)*32 + seg16;
        const __nv_bfloat16* aS = (sg == 1) ? g_sumL : g_sumH;
        const __nv_bfloat16* bS = (sg == 2) ? g_atnL : g_atnH;
        uint32_t aT = sA + buf*TILE_B, bT = sB + buf*TILE_B;
#pragma unroll
        for (int i = 0; i < 2; i++) {
            int row = r0 + i*64;
            int gn = n0 + row;
            bool vb = gn < PP;
            const __nv_bfloat16* pa = aS + ((size_t)zp*CC + m0 + row)*PP + k0;
            const __nv_bfloat16* pb = bS + ((size_t)z*PP + (vb ? gn : 0))*PP + k0;
            uint32_t o = (uint32_t)(row*TSTRIDE + seg16)*2;
            cp16(aT + o, pa, true);
            cp16(bT + o, pb, vb);
        }
    };

    const int NT = 150;
    stage(0, 0); CP_COMMIT();
    for (int t = 0; t < NT; t++) {
        CP_WAIT0(); __syncthreads();
        if (t+1 < NT) { stage(t+1, (t+1)&1); CP_COMMIT(); }
        compute_chunk(sA + (t&1)*TILE_B, sB + (t&1)*TILE_B, lane, wm, wn, acc);
        __syncthreads();
    }
    epilogue(acc, Cp, m0, n0, CC, PP, nullptr, lane, wm, wn);
}

// ============ conv3x3 as GEMM: K' = 3*9*512 = 13824 ============
__global__ __launch_bounds__(256) void conv_mma(const __nv_bfloat16* __restrict__ wH,
                                                const __nv_bfloat16* __restrict__ wL,
                                                const float* __restrict__ bias,
                                                const __nv_bfloat16* __restrict__ x1H,
                                                const __nv_bfloat16* __restrict__ x1L,
                                                float* __restrict__ out, int OC) {
    __shared__ alignas(16) __nv_bfloat16 As[2][128][TSTRIDE];
    __shared__ alignas(16) __nv_bfloat16 Bs[2][128][TSTRIDE];
    const int tid = threadIdx.x, lane = tid & 31, wid = tid >> 5;
    const int wm = wid & 1, wn = wid >> 1;
    const int z = blockIdx.z;
    const int m0 = blockIdx.y*128, n0 = blockIdx.x*128;
    float* pO = out + (size_t)z*OC*PP;
    const uint32_t sA = smem_u32(As), sB = smem_u32(Bs);

    const int r0 = tid >> 2, seg16 = (tid & 3)*8;
    int gn0 = n0 + r0,        y0 = gn0 / WW, x0 = gn0 % WW;
    int gn1 = n0 + r0 + 64,   y1 = gn1 / WW, x1c = gn1 % WW;
    float acc[4][4][4] = {};

    auto stage = [&](int t, int buf) {
        int sg = t / 144;
        int kk = (t % 144)*32;
        int s  = kk >> 9;
        int cw = kk & 511;
        int ky = s/3 - 1, kx = s%3 - 1;
        const __nv_bfloat16* aS = (sg == 1) ? wL : wH;
        const __nv_bfloat16* bS;
        if (cw < 256) bS = (sg == 2) ? g_aggTL : g_aggTH;
        else          bS = (sg == 2) ? x1L : x1H;
        int ci = (cw & 255) + seg16;
        uint32_t aT = sA + buf*TILE_B, bT = sB + buf*TILE_B;
#pragma unroll
        for (int i = 0; i < 2; i++) {
            int row = r0 + i*64;
            const __nv_bfloat16* pa = aS + ((size_t)s*OC + m0 + row)*512 + cw + seg16;
            int yy = (i ? y1 : y0) + ky, xx = (i ? x1c : x0) + kx;
            int gnr = i ? gn1 : gn0;
            bool vb = (gnr < PP) && yy >= 0 && yy < HH && xx >= 0 && xx < WW;
            int sp = vb ? (yy*WW + xx) : 0;
            const __nv_bfloat16* pb = bS + ((size_t)z*PP + sp)*256 + ci;
            uint32_t o = (uint32_t)(row*TSTRIDE + seg16)*2;
            cp16(aT + o, pa, true);
            cp16(bT + o, pb, vb);
        }
    };

    const int NT = 432;
    stage(0, 0); CP_COMMIT();
    for (int t = 0; t < NT; t++) {
        CP_WAIT0(); __syncthreads();
        if (t+1 < NT) { stage(t+1, (t+1)&1); CP_COMMIT(); }
        compute_chunk(sA + (t&1)*TILE_B, sB + (t&1)*TILE_B, lane, wm, wn, acc);
        __syncthreads();
    }
    epilogue(acc, pO, m0, n0, OC, PP, bias, lane, wm, wn);
}

// ============ theta GEMM (SIMT fp32, small) ============
#define BM 128
#define BN 128
#define BK 16
#define LDT 132
__device__ __forceinline__ void compute16(const float (*As)[LDT], const float (*Bs)[LDT],
                                          float acc[8][8], int tx, int ty) {
#pragma unroll
    for (int kk = 0; kk < BK; kk++) {
        float4 a0 = *(const float4*)(&As[kk][ty*4]);
        float4 a1 = *(const float4*)(&As[kk][64 + ty*4]);
        float4 b0 = *(const float4*)(&Bs[kk][tx*4]);
        float4 b1 = *(const float4*)(&Bs[kk][64 + tx*4]);
        float a[8] = {a0.x,a0.y,a0.z,a0.w,a1.x,a1.y,a1.z,a1.w};
        float b[8] = {b0.x,b0.y,b0.z,b0.w,b1.x,b1.y,b1.z,b1.w};
#pragma unroll
        for (int i = 0; i < 8; i++)
#pragma unroll
            for (int j = 0; j < 8; j++)
                acc[i][j] += a[i]*b[j];
    }
}
__device__ __forceinline__ int mmap8(int ty, int i) { return (i<4) ? ty*4+i : 64+ty*4+(i-4); }

__global__ __launch_bounds__(256) void theta_gemm(const float* __restrict__ W,
                                                  const float* __restrict__ bias) {
    const int z = blockIdx.z;
    const float* Bp = g_nodes + (size_t)z*CP;
    float* Cp = g_th + (size_t)z*CP;
    const int m0 = blockIdx.y*BM, n0 = blockIdx.x*BN;
    __shared__ alignas(16) float As[2][BK][LDT];
    __shared__ alignas(16) float Bs[2][BK][LDT];
    const int tid = threadIdx.x, tx = tid & 15, ty = tid >> 4;
    const int am = tid >> 1, ak = (tid & 1)*8;
    const int bn4 = tid & 31, bk = tid >> 5;
    const bool nfull = (n0 + BN) <= PP;
    float acc[8][8] = {};
    float ra[8], rb[8];
    const int NT = CC/BK;

    auto loadA = [&](int t) {
        const float* p = W + (size_t)(m0+am)*CC + t*BK + ak;
        float4 v0 = *(const float4*)p, v1 = *(const float4*)(p+4);
        ra[0]=v0.x; ra[1]=v0.y; ra[2]=v0.z; ra[3]=v0.w;
        ra[4]=v1.x; ra[5]=v1.y; ra[6]=v1.z; ra[7]=v1.w;
    };
    auto loadB = [&](int t) {
        const float* p = Bp + (size_t)(t*BK + bk)*PP + n0 + bn4*4;
        if (nfull) {
            float4 v0 = *(const float4*)p, v1 = *(const float4*)(p + 8*PP);
            rb[0]=v0.x; rb[1]=v0.y; rb[2]=v0.z; rb[3]=v0.w;
            rb[4]=v1.x; rb[5]=v1.y; rb[6]=v1.z; rb[7]=v1.w;
        } else {
            int gb = n0 + bn4*4;
#pragma unroll
            for (int e = 0; e < 4; e++) {
                rb[e]   = (gb+e < PP) ? p[e]        : 0.f;
                rb[e+4] = (gb+e < PP) ? p[8*PP + e] : 0.f;
            }
        }
    };
    auto store = [&](int buf) {
#pragma unroll
        for (int j = 0; j < 8; j++) As[buf][ak+j][am] = ra[j];
        *(float4*)&Bs[buf][bk][bn4*4]   = make_float4(rb[0],rb[1],rb[2],rb[3]);
        *(float4*)&Bs[buf][bk+8][bn4*4] = make_float4(rb[4],rb[5],rb[6],rb[7]);
    };

    loadA(0); loadB(0); store(0); __syncthreads();
    for (int t = 1; t < NT; t++) {
        loadA(t); loadB(t);
        compute16(As[(t-1)&1], Bs[(t-1)&1], acc, tx, ty);
        store(t&1);
        __syncthreads();
    }
    compute16(As[(NT-1)&1], Bs[(NT-1)&1], acc, tx, ty);

#pragma unroll
    for (int i = 0; i < 8; i++) {
        int m = m0 + mmap8(ty, i); float bv = bias[m];
#pragma unroll
        for (int j = 0; j < 8; j++) {
            int n = n0 + mmap8(tx, j);
            if (n < PP) Cp[(size_t)m*PP + n] = acc[i][j] + bv;
        }
    }
}

// ============ softmax rows -> bf16 hi/lo attention ============
__device__ __forceinline__ float block_reduce(float v, bool is_max) {
    __shared__ float s[32];
    __syncthreads();
#pragma unroll
    for (int o = 16; o > 0; o >>= 1) {
        float t = __shfl_xor_sync(0xffffffffu, v, o);
        v = is_max ? fmaxf(v, t) : (v + t);
    }
    const int w = threadIdx.x >> 5, l = threadIdx.x & 31;
    if (l == 0) s[w] = v;
    __syncthreads();
    if (w == 0) {
        v = (l < 8) ? s[l] : (is_max ? -INFINITY : 0.f);
#pragma unroll
        for (int o = 4; o > 0; o >>= 1) {
            float t = __shfl_xor_sync(0xffffffffu, v, o);
            v = is_max ? fmaxf(v, t) : (v + t);
        }
        if (l == 0) s[0] = v;
    }
    __syncthreads();
    return s[0];
}

__global__ __launch_bounds__(256) void softmax_bf() {
    const size_t row = blockIdx.x;
    const float* srow = g_scores + row*PP;
    __nv_bfloat16* hrow = g_atnH + row*PP;
    __nv_bfloat16* lrow = g_atnL + row*PP;
    const int t = threadIdx.x;
    float v[7];
    float mx = -INFINITY;
#pragma unroll
    for (int i = 0; i < 7; i++) {
        int idx = t + i*256;
        v[i] = (idx < PP) ? srow[idx] : -INFINITY;
        mx = fmaxf(mx, v[i]);
    }
    mx = block_reduce(mx, true);
    float sum = 0.f;
#pragma unroll
    for (int i = 0; i < 7; i++) {
        int idx = t + i*256;
        if (idx < PP) { v[i] = __expf(v[i] - mx); sum += v[i]; }
    }
    sum = block_reduce(sum, false);
    const float inv = 1.f / sum;
#pragma unroll
    for (int i = 0; i < 7; i++) {
        int idx = t + i*256;
        if (idx < PP) {
            float a = v[i] * inv;
            __nv_bfloat16 h = __float2bfloat16(a);
            __nv_bfloat16 l = __float2bfloat16(a - __bfloat162float(h));
            hrow[idx] = h; lrow[idx] = l;
        }
    }
}

// ============ split / transpose prep kernels ============
__device__ __forceinline__ void bsplit(float v, __nv_bfloat16* h, __nv_bfloat16* l) {
    __nv_bfloat16 hh = __float2bfloat16(v);
    *h = hh;
    *l = __float2bfloat16(v - __bfloat162float(hh));
}

// [z][c][p] fp32 -> [z][p][c] bf16 hi/lo
__global__ __launch_bounds__(256) void splitT_kernel(const float* __restrict__ src,
                                                     __nv_bfloat16* __restrict__ dh,
                                                     __nv_bfloat16* __restrict__ dl) {
    size_t i = (size_t)blockIdx.x*256 + threadIdx.x;
    if (i >= (size_t)NBCP) return;
    int c = (int)(i & 255);
    int p = (int)((i >> 8) % PP);
    int z = (int)(i / ((size_t)PP*256));
    float v = src[(size_t)z*CP + (size_t)c*PP + p];
    bsplit(v, &dh[i], &dl[i]);
}

__global__ __launch_bounds__(256) void sum_split() {
    size_t i = (size_t)blockIdx.x*256 + threadIdx.x;
    if (i >= (size_t)NN*BCP) return;
    int z2 = (int)(i / CP); size_t cp = i % CP;
    int pr = z2 >> 2, b = z2 & 3;
    float v = g_nodes[(size_t)(c_p0[pr]*BB + b)*CP + cp] +
              g_nodes[(size_t)(c_p1[pr]*BB + b)*CP + cp];
    bsplit(v, &g_sumH[i], &g_sumL[i]);
}

// agg = msg over incoming edges; FIXED edge indexing:
// g_msg is [e][b][c][p] (z_e = e*BB+b); node n receives edges e=2n and e=2n+1,
// so slices (2n)*BB+b = 8n+b and (2n+1)*BB+b = 8n+4+b (NOT 2*z, 2*z+1 with z=n*4+b).
__global__ __launch_bounds__(256) void aggT_split() {
    size_t i = (size_t)blockIdx.x*256 + threadIdx.x;
    if (i >= (size_t)NBCP) return;
    int c = (int)(i & 255);
    int p = (int)((i >> 8) % PP);
    int z = (int)(i / ((size_t)PP*256));   // z = n*4 + b
    int n = z >> 2, b = z & 3;
    size_t off = (size_t)c*PP + p;
    float v = g_msg[(size_t)(8*n + b)*CP + off] +
              g_msg[(size_t)(8*n + 4 + b)*CP + off];
    bsplit(v, &g_aggTH[i], &g_aggTL[i]);
}

__global__ __launch_bounds__(256) void rhT_split() {
    size_t i = (size_t)blockIdx.x*256 + threadIdx.x;
    if (i >= (size_t)NBCP) return;
    int c = (int)(i & 255);
    int p = (int)((i >> 8) % PP);
    int z = (int)(i / ((size_t)PP*256));
    size_t off = (size_t)c*PP + p;
    float g = g_gates[(size_t)z*512*PP + off];
    float rr = 1.f / (1.f + __expf(-g));
    float v = rr * g_nodes[(size_t)z*CP + off];
    bsplit(v, &g_rhTH[i], &g_rhTL[i]);
}

__global__ __launch_bounds__(256) void update_kernel() {
    size_t i = (size_t)blockIdx.x*256 + threadIdx.x;
    if (i >= (size_t)NBCP) return;
    size_t nb = i / CP, cp = i % CP;
    float gz = g_gates[nb*(size_t)(512*PP) + (size_t)CC*PP + cp];
    float zv = 1.f / (1.f + __expf(-gz));
    float h = g_nodes[i];
    float cd = tanhf(g_cand[i]);
    g_nodes[i] = (1.f - zv)*h + zv*cd;
}

// w[oc][ci][3][3] -> [s][oc][ci] bf16 hi/lo
__global__ __launch_bounds__(256) void wsplit(const float* __restrict__ w,
                                              __nv_bfloat16* __restrict__ dh,
                                              __nv_bfloat16* __restrict__ dl, int OC) {
    size_t i = (size_t)blockIdx.x*256 + threadIdx.x;
    size_t total = (size_t)9*OC*512;
    if (i >= total) return;
    int ci = (int)(i & 511);
    int oc = (int)((i >> 9) % OC);
    int s  = (int)(i / ((size_t)OC*512));
    float v = w[((size_t)oc*512 + ci)*9 + s];
    bsplit(v, &dh[i], &dl[i]);
}

__global__ __launch_bounds__(256) void copy_in(const float* __restrict__ src) {
    size_t i = (size_t)blockIdx.x*256 + threadIdx.x;
    if (i < (size_t)NBCP/4) ((float4*)g_nodes)[i] = ((const float4*)src)[i];
}
__global__ __launch_bounds__(256) void copy_out(float* __restrict__ dst) {
    size_t i = (size_t)blockIdx.x*256 + threadIdx.x;
    if (i < (size_t)NBCP/4) ((float4*)dst)[i] = ((const float4*)g_nodes)[i];
}

// ---------------- host launch ----------------
extern "C" void kernel_launch(void* const* d_in, const int* in_sizes, int n_in,
                              void* d_out, int out_size) {
    const float* in_nodes = (const float*)d_in[0];
    const float* theta_w  = (const float*)d_in[1];
    const float* theta_b  = (const float*)d_in[2];
    const float* gw       = (const float*)d_in[3];
    const float* gb       = (const float*)d_in[4];
    const float* cw       = (const float*)d_in[5];
    const float* cb       = (const float*)d_in[6];
    float* out = (float*)d_out;

    __nv_bfloat16 *p_wgH, *p_wgL, *p_wcH, *p_wcL, *p_nTH, *p_nTL, *p_rhH, *p_rhL;
    __nv_bfloat16 *p_thH, *p_thL;
    float *p_nodes, *p_th, *p_gates, *p_cand;
    cudaGetSymbolAddress((void**)&p_wgH, g_wgH);
    cudaGetSymbolAddress((void**)&p_wgL, g_wgL);
    cudaGetSymbolAddress((void**)&p_wcH, g_wcH);
    cudaGetSymbolAddress((void**)&p_wcL, g_wcL);
    cudaGetSymbolAddress((void**)&p_nTH, g_nodesTH);
    cudaGetSymbolAddress((void**)&p_nTL, g_nodesTL);
    cudaGetSymbolAddress((void**)&p_rhH, g_rhTH);
    cudaGetSymbolAddress((void**)&p_rhL, g_rhTL);
    cudaGetSymbolAddress((void**)&p_thH, g_thTH);
    cudaGetSymbolAddress((void**)&p_thL, g_thTL);
    cudaGetSymbolAddress((void**)&p_nodes, g_nodes);
    cudaGetSymbolAddress((void**)&p_th,    g_th);
    cudaGetSymbolAddress((void**)&p_gates, g_gates);
    cudaGetSymbolAddress((void**)&p_cand,  g_cand);

    copy_in<<<(NBCP/4 + 255)/256, 256>>>(in_nodes);
    wsplit<<<((size_t)9*512*512 + 255)/256, 256>>>(gw, p_wgH, p_wgL, 512);
    wsplit<<<((size_t)9*256*512 + 255)/256, 256>>>(cw, p_wcH, p_wcL, 256);

    const int EW = NBCP/256;  // 19200
    for (int pass = 0; pass < 2; pass++) {
        theta_gemm <<<dim3(13, 2, NBB), 256>>>(theta_w, theta_b);
        splitT_kernel<<<EW, 256>>>(p_nodes, p_nTH, p_nTL);
        splitT_kernel<<<EW, 256>>>(p_th, p_thH, p_thL);
        sum_split<<<EW, 256>>>();
        scores_mma<<<dim3(13, 13, EE*BB), 256>>>();
        softmax_bf<<<EE*BB*PP, 256>>>();
        msg_mma<<<dim3(13, 2, EE*BB), 256>>>();
        aggT_split<<<EW, 256>>>();
        conv_mma<<<dim3(13, 4, NBB), 256>>>(p_wgH, p_wgL, gb, p_nTH, p_nTL, p_gates, 512);
        rhT_split<<<EW, 256>>>();
        conv_mma<<<dim3(13, 2, NBB), 256>>>(p_wcH, p_wcL, cb, p_rhH, p_rhL, p_cand, 256);
        update_kernel<<<EW, 256>>>();
    }
    copy_out<<<(NBCP/4 + 255)/256, 256>>>(out);
}

// round 6
// speedup vs baseline: 3.1545x; 1.2469x over previous
#include <cuda_runtime.h>
#include <cuda_fp16.h>
#include <math.h>
#include <stdint.h>

// ---------------- problem constants ----------------
#define NN   3
#define BB   4
#define CC   256
#define HH   40
#define WW   40
#define PP   (HH*WW)           // 1600
#define EE   6
#define NBB  (NN*BB)           // 12
#define CP   (CC*PP)           // 409600
#define BCP  (BB*CP)
#define NBCP (NN*BCP)          // 4915200

// ---------------- scratch ----------------
__device__ float g_nodes [NBCP];
__device__ float g_th    [NBCP];
__device__ float g_scores[(size_t)EE*BB*PP*PP];
__device__ float g_msg   [(size_t)EE*BCP];
__device__ float g_gates [(size_t)NBB*512*PP];
__device__ float g_cand  [NBCP];

// fp16 hi/lo split buffers (16B-aligned for cp.async)
__device__ __align__(16) __half g_atnH[(size_t)EE*BB*PP*PP];
__device__ __align__(16) __half g_atnL[(size_t)EE*BB*PP*PP];
__device__ __align__(16) __half g_nodesTH[NBCP], g_nodesTL[NBCP]; // [z][p][c]
__device__ __align__(16) __half g_thTH[NBCP],    g_thTL[NBCP];    // [z][p][c]
__device__ __align__(16) __half g_sumH[NN*BCP],  g_sumL[NN*BCP];  // [pair*b][c][q]
__device__ __align__(16) __half g_aggTH[NBCP];                    // [z][p][c] (H only)
__device__ __align__(16) __half g_rhTH[NBCP];                     // [z][p][c] (H only)
__device__ __align__(16) __half g_wgH[9*512*512], g_wgL[9*512*512]; // [s][oc][ci]
__device__ __align__(16) __half g_wcH[9*256*512], g_wcL[9*256*512];

__device__ __constant__ int c_recv[EE] = {0,0,1,1,2,2};
__device__ __constant__ int c_send[EE] = {1,2,0,2,0,1};
__device__ __constant__ int c_pair[EE] = {0,1,0,2,1,2};
__device__ __constant__ int c_p0[NN]   = {0,0,1};
__device__ __constant__ int c_p1[NN]   = {1,2,2};

// ================= low-level helpers (portable PTX only) =================
__device__ __forceinline__ uint32_t smem_u32(const void* p) {
    uint32_t a;
    asm("{ .reg .u64 t; cvta.to.shared.u64 t, %1; cvt.u32.u64 %0, t; }" : "=r"(a) : "l"(p));
    return a;
}
__device__ __forceinline__ void cp16(uint32_t dst, const void* src, bool v) {
    asm volatile("cp.async.cg.shared.global [%0], [%1], 16, %2;"
                 :: "r"(dst), "l"(src), "r"(v ? 16 : 0));
}
#define CP_COMMIT() asm volatile("cp.async.commit_group;" ::: "memory")
#define CP_WAIT1()  asm volatile("cp.async.wait_group 1;" ::: "memory")

__device__ __forceinline__ void ldsm4(uint32_t (&r)[4], uint32_t addr) {
    asm volatile("ldmatrix.sync.aligned.m8n8.x4.shared.b16 {%0,%1,%2,%3}, [%4];"
                 : "=r"(r[0]), "=r"(r[1]), "=r"(r[2]), "=r"(r[3]) : "r"(addr));
}
__device__ __forceinline__ void mma16816(float* c, const uint32_t (&a)[4],
                                         uint32_t b0, uint32_t b1) {
    asm volatile("mma.sync.aligned.m16n8k16.row.col.f32.f16.f16.f32 "
                 "{%0,%1,%2,%3}, {%4,%5,%6,%7}, {%8,%9}, {%0,%1,%2,%3};"
                 : "+f"(c[0]), "+f"(c[1]), "+f"(c[2]), "+f"(c[3])
                 : "r"(a[0]), "r"(a[1]), "r"(a[2]), "r"(a[3]), "r"(b0), "r"(b1));
}

// ---------------- tile geometry ----------------
#define TSTRIDE 40
#define TILE_B  (128*TSTRIDE*2)   // 10240 bytes per tile buffer

__device__ __forceinline__ void compute_chunk(uint32_t aT, uint32_t bT,
                                              int lane, int wm, int wn,
                                              float (*acc)[4][4]) {
    const int arow = wm*64 + ((lane>>3)&1)*8 + (lane&7);
    const int acol = (lane>>4)*8;
    const int brow = wn*32 + ((lane>>4)&1)*8 + (lane&7);
    const int bcol = ((lane>>3)&1)*8;
#pragma unroll
    for (int ks = 0; ks < 2; ks++) {
        uint32_t a[4][4], b[2][4];
#pragma unroll
        for (int mt = 0; mt < 4; mt++)
            ldsm4(a[mt], aT + (uint32_t)(((arow + mt*16)*TSTRIDE) + acol + ks*16)*2);
#pragma unroll
        for (int np = 0; np < 2; np++)
            ldsm4(b[np], bT + (uint32_t)(((brow + np*16)*TSTRIDE) + bcol + ks*16)*2);
#pragma unroll
        for (int mt = 0; mt < 4; mt++)
#pragma unroll
            for (int nt = 0; nt < 4; nt++)
                mma16816(acc[mt][nt], a[mt], b[nt>>1][(nt&1)*2], b[nt>>1][(nt&1)*2+1]);
    }
}

__device__ __forceinline__ void epilogue(float (*acc)[4][4], float* out,
                                         int m0, int n0, int Mtot, int Ntot,
                                         const float* bias, int lane, int wm, int wn) {
#pragma unroll
    for (int mt = 0; mt < 4; mt++) {
        int m = m0 + wm*64 + mt*16 + (lane>>2);
        float bv0 = (bias && m < Mtot) ? bias[m] : 0.f;
        float bv1 = (bias && m+8 < Mtot) ? bias[m+8] : 0.f;
#pragma unroll
        for (int nt = 0; nt < 4; nt++) {
            int n = n0 + wn*32 + nt*8 + (lane&3)*2;
            if (n >= Ntot) continue;
            if (m < Mtot) {
                float2 v = make_float2(acc[mt][nt][0] + bv0, acc[mt][nt][1] + bv0);
                *(float2*)&out[(size_t)m*Ntot + n] = v;
            }
            if (m+8 < Mtot) {
                float2 v = make_float2(acc[mt][nt][2] + bv1, acc[mt][nt][3] + bv1);
                *(float2*)&out[(size_t)(m+8)*Ntot + n] = v;
            }
        }
    }
}

// 3-stage pipeline driver macro body shared by the GEMM kernels (written inline)

// ============ scores: S[p][q] = sum_c th[p][c] * nodes[q][c], fp16 3-seg, K'=768 ============
__global__ __launch_bounds__(256) void scores_mma() {
    __shared__ alignas(16) __half As[3][128][TSTRIDE];
    __shared__ alignas(16) __half Bs[3][128][TSTRIDE];
    const int tid = threadIdx.x, lane = tid & 31, wid = tid >> 5;
    const int wm = wid & 1, wn = wid >> 1;
    const int z = blockIdx.z, e = z >> 2, b = z & 3;
    const int zr = c_recv[e]*BB + b, zs = c_send[e]*BB + b;
    const int m0 = blockIdx.y*128, n0 = blockIdx.x*128;
    float* Cp = g_scores + (size_t)z*PP*PP;
    const uint32_t sA = smem_u32(As), sB = smem_u32(Bs);

    const int r0 = tid >> 2, seg16 = (tid & 3)*8;
    float acc[4][4][4] = {};

    auto stage = [&](int t, int buf) {
        int sg = t >> 3, k0 = (t & 7)*32 + seg16;
        const __half* aS = (sg == 1) ? g_thTL : g_thTH;
        const __half* bS = (sg == 2) ? g_nodesTL : g_nodesTH;
        uint32_t aT = sA + buf*TILE_B, bT = sB + buf*TILE_B;
#pragma unroll
        for (int i = 0; i < 2; i++) {
            int row = r0 + i*64;
            int gm = m0 + row, gn = n0 + row;
            bool va = gm < PP, vb = gn < PP;
            const __half* pa = aS + ((size_t)zr*PP + (va ? gm : 0))*256 + k0;
            const __half* pb = bS + ((size_t)zs*PP + (vb ? gn : 0))*256 + k0;
            uint32_t o = (uint32_t)(row*TSTRIDE + seg16)*2;
            cp16(aT + o, pa, va);
            cp16(bT + o, pb, vb);
        }
    };

    const int NT = 24;
    stage(0, 0); CP_COMMIT();
    stage(1, 1); CP_COMMIT();
    for (int t = 0; t < NT; t++) {
        CP_WAIT1(); __syncthreads();
        if (t+2 < NT) { stage(t+2, (t+2)%3); CP_COMMIT(); }
        compute_chunk(sA + (t%3)*TILE_B, sB + (t%3)*TILE_B, lane, wm, wn, acc);
        __syncthreads();
    }
    epilogue(acc, Cp, m0, n0, PP, PP, nullptr, lane, wm, wn);
}

// ============ msg: M[c][p] = sum_q sum[c][q] * atn[p][q], fp16 3-seg, K'=4800 ============
__global__ __launch_bounds__(256) void msg_mma() {
    __shared__ alignas(16) __half As[3][128][TSTRIDE];
    __shared__ alignas(16) __half Bs[3][128][TSTRIDE];
    const int tid = threadIdx.x, lane = tid & 31, wid = tid >> 5;
    const int wm = wid & 1, wn = wid >> 1;
    const int z = blockIdx.z, e = z >> 2, b = z & 3;
    const int zp = c_pair[e]*BB + b;
    const int m0 = blockIdx.y*128, n0 = blockIdx.x*128;
    float* Cp = g_msg + (size_t)z*CP;
    const uint32_t sA = smem_u32(As), sB = smem_u32(Bs);

    const int r0 = tid >> 2, seg16 = (tid & 3)*8;
    float acc[4][4][4] = {};

    auto stage = [&](int t, int buf) {
        int sg = t / 50, k0 = (t % 50)*32 + seg16;
        const __half* aS = (sg == 1) ? g_sumL : g_sumH;
        const __half* bS = (sg == 2) ? g_atnL : g_atnH;
        uint32_t aT = sA + buf*TILE_B, bT = sB + buf*TILE_B;
#pragma unroll
        for (int i = 0; i < 2; i++) {
            int row = r0 + i*64;
            int gn = n0 + row;
            bool vb = gn < PP;
            const __half* pa = aS + ((size_t)zp*CC + m0 + row)*PP + k0;
            const __half* pb = bS + ((size_t)z*PP + (vb ? gn : 0))*PP + k0;
            uint32_t o = (uint32_t)(row*TSTRIDE + seg16)*2;
            cp16(aT + o, pa, true);
            cp16(bT + o, pb, vb);
        }
    };

    const int NT = 150;
    stage(0, 0); CP_COMMIT();
    stage(1, 1); CP_COMMIT();
    for (int t = 0; t < NT; t++) {
        CP_WAIT1(); __syncthreads();
        if (t+2 < NT) { stage(t+2, (t+2)%3); CP_COMMIT(); }
        compute_chunk(sA + (t%3)*TILE_B, sB + (t%3)*TILE_B, lane, wm, wn, acc);
        __syncthreads();
    }
    epilogue(acc, Cp, m0, n0, CC, PP, nullptr, lane, wm, wn);
}

// ============ conv3x3 as GEMM: fp16 2-seg ([wH|wL]*[xH|xH]), K' = 2*4608 = 9216 ============
__global__ __launch_bounds__(256) void conv_mma(const __half* __restrict__ wH,
                                                const __half* __restrict__ wL,
                                                const float* __restrict__ bias,
                                                const __half* __restrict__ x1H,
                                                float* __restrict__ out, int OC) {
    __shared__ alignas(16) __half As[3][128][TSTRIDE];
    __shared__ alignas(16) __half Bs[3][128][TSTRIDE];
    const int tid = threadIdx.x, lane = tid & 31, wid = tid >> 5;
    const int wm = wid & 1, wn = wid >> 1;
    const int z = blockIdx.z;
    const int m0 = blockIdx.y*128, n0 = blockIdx.x*128;
    float* pO = out + (size_t)z*OC*PP;
    const uint32_t sA = smem_u32(As), sB = smem_u32(Bs);

    const int r0 = tid >> 2, seg16 = (tid & 3)*8;
    int gn0 = n0 + r0,        y0 = gn0 / WW, x0 = gn0 % WW;
    int gn1 = n0 + r0 + 64,   y1 = gn1 / WW, x1c = gn1 % WW;
    float acc[4][4][4] = {};

    auto stage = [&](int t, int buf) {
        int sg = t / 144;                 // 0: wH, 1: wL  (B always H)
        int kk = (t % 144)*32;
        int s  = kk >> 9;
        int cw = kk & 511;
        int ky = s/3 - 1, kx = s%3 - 1;
        const __half* aS = (sg == 1) ? wL : wH;
        const __half* bS = (cw < 256) ? g_aggTH : x1H;
        int ci = (cw & 255) + seg16;
        uint32_t aT = sA + buf*TILE_B, bT = sB + buf*TILE_B;
#pragma unroll
        for (int i = 0; i < 2; i++) {
            int row = r0 + i*64;
            const __half* pa = aS + ((size_t)s*OC + m0 + row)*512 + cw + seg16;
            int yy = (i ? y1 : y0) + ky, xx = (i ? x1c : x0) + kx;
            int gnr = i ? gn1 : gn0;
            bool vb = (gnr < PP) && yy >= 0 && yy < HH && xx >= 0 && xx < WW;
            int sp = vb ? (yy*WW + xx) : 0;
            const __half* pb = bS + ((size_t)z*PP + sp)*256 + ci;
            uint32_t o = (uint32_t)(row*TSTRIDE + seg16)*2;
            cp16(aT + o, pa, true);
            cp16(bT + o, pb, vb);
        }
    };

    const int NT = 288;
    stage(0, 0); CP_COMMIT();
    stage(1, 1); CP_COMMIT();
    for (int t = 0; t < NT; t++) {
        CP_WAIT1(); __syncthreads();
        if (t+2 < NT) { stage(t+2, (t+2)%3); CP_COMMIT(); }
        compute_chunk(sA + (t%3)*TILE_B, sB + (t%3)*TILE_B, lane, wm, wn, acc);
        __syncthreads();
    }
    epilogue(acc, pO, m0, n0, OC, PP, bias, lane, wm, wn);
}

// ============ theta GEMM (SIMT fp32, small) ============
#define BM 128
#define BN 128
#define BK 16
#define LDT 132
__device__ __forceinline__ void compute16(const float (*As)[LDT], const float (*Bs)[LDT],
                                          float acc[8][8], int tx, int ty) {
#pragma unroll
    for (int kk = 0; kk < BK; kk++) {
        float4 a0 = *(const float4*)(&As[kk][ty*4]);
        float4 a1 = *(const float4*)(&As[kk][64 + ty*4]);
        float4 b0 = *(const float4*)(&Bs[kk][tx*4]);
        float4 b1 = *(const float4*)(&Bs[kk][64 + tx*4]);
        float a[8] = {a0.x,a0.y,a0.z,a0.w,a1.x,a1.y,a1.z,a1.w};
        float b[8] = {b0.x,b0.y,b0.z,b0.w,b1.x,b1.y,b1.z,b1.w};
#pragma unroll
        for (int i = 0; i < 8; i++)
#pragma unroll
            for (int j = 0; j < 8; j++)
                acc[i][j] += a[i]*b[j];
    }
}
__device__ __forceinline__ int mmap8(int ty, int i) { return (i<4) ? ty*4+i : 64+ty*4+(i-4); }

__global__ __launch_bounds__(256) void theta_gemm(const float* __restrict__ W,
                                                  const float* __restrict__ bias) {
    const int z = blockIdx.z;
    const float* Bp = g_nodes + (size_t)z*CP;
    float* Cp = g_th + (size_t)z*CP;
    const int m0 = blockIdx.y*BM, n0 = blockIdx.x*BN;
    __shared__ alignas(16) float As[2][BK][LDT];
    __shared__ alignas(16) float Bs[2][BK][LDT];
    const int tid = threadIdx.x, tx = tid & 15, ty = tid >> 4;
    const int am = tid >> 1, ak = (tid & 1)*8;
    const int bn4 = tid & 31, bk = tid >> 5;
    const bool nfull = (n0 + BN) <= PP;
    float acc[8][8] = {};
    float ra[8], rb[8];
    const int NT = CC/BK;

    auto loadA = [&](int t) {
        const float* p = W + (size_t)(m0+am)*CC + t*BK + ak;
        float4 v0 = *(const float4*)p, v1 = *(const float4*)(p+4);
        ra[0]=v0.x; ra[1]=v0.y; ra[2]=v0.z; ra[3]=v0.w;
        ra[4]=v1.x; ra[5]=v1.y; ra[6]=v1.z; ra[7]=v1.w;
    };
    auto loadB = [&](int t) {
        const float* p = Bp + (size_t)(t*BK + bk)*PP + n0 + bn4*4;
        if (nfull) {
            float4 v0 = *(const float4*)p, v1 = *(const float4*)(p + 8*PP);
            rb[0]=v0.x; rb[1]=v0.y; rb[2]=v0.z; rb[3]=v0.w;
            rb[4]=v1.x; rb[5]=v1.y; rb[6]=v1.z; rb[7]=v1.w;
        } else {
            int gb = n0 + bn4*4;
#pragma unroll
            for (int e = 0; e < 4; e++) {
                rb[e]   = (gb+e < PP) ? p[e]        : 0.f;
                rb[e+4] = (gb+e < PP) ? p[8*PP + e] : 0.f;
            }
        }
    };
    auto store = [&](int buf) {
#pragma unroll
        for (int j = 0; j < 8; j++) As[buf][ak+j][am] = ra[j];
        *(float4*)&Bs[buf][bk][bn4*4]   = make_float4(rb[0],rb[1],rb[2],rb[3]);
        *(float4*)&Bs[buf][bk+8][bn4*4] = make_float4(rb[4],rb[5],rb[6],rb[7]);
    };

    loadA(0); loadB(0); store(0); __syncthreads();
    for (int t = 1; t < NT; t++) {
        loadA(t); loadB(t);
        compute16(As[(t-1)&1], Bs[(t-1)&1], acc, tx, ty);
        store(t&1);
        __syncthreads();
    }
    compute16(As[(NT-1)&1], Bs[(NT-1)&1], acc, tx, ty);

#pragma unroll
    for (int i = 0; i < 8; i++) {
        int m = m0 + mmap8(ty, i); float bv = bias[m];
#pragma unroll
        for (int j = 0; j < 8; j++) {
            int n = n0 + mmap8(tx, j);
            if (n < PP) Cp[(size_t)m*PP + n] = acc[i][j] + bv;
        }
    }
}

// ============ softmax rows -> fp16 hi/lo attention ============
__device__ __forceinline__ float block_reduce(float v, bool is_max) {
    __shared__ float s[32];
    __syncthreads();
#pragma unroll
    for (int o = 16; o > 0; o >>= 1) {
        float t = __shfl_xor_sync(0xffffffffu, v, o);
        v = is_max ? fmaxf(v, t) : (v + t);
    }
    const int w = threadIdx.x >> 5, l = threadIdx.x & 31;
    if (l == 0) s[w] = v;
    __syncthreads();
    if (w == 0) {
        v = (l < 8) ? s[l] : (is_max ? -INFINITY : 0.f);
#pragma unroll
        for (int o = 4; o > 0; o >>= 1) {
            float t = __shfl_xor_sync(0xffffffffu, v, o);
            v = is_max ? fmaxf(v, t) : (v + t);
        }
        if (l == 0) s[0] = v;
    }
    __syncthreads();
    return s[0];
}

__global__ __launch_bounds__(256) void softmax_fp() {
    const size_t row = blockIdx.x;
    const float* srow = g_scores + row*PP;
    __half* hrow = g_atnH + row*PP;
    __half* lrow = g_atnL + row*PP;
    const int t = threadIdx.x;
    float v[7];
    float mx = -INFINITY;
#pragma unroll
    for (int i = 0; i < 7; i++) {
        int idx = t + i*256;
        v[i] = (idx < PP) ? srow[idx] : -INFINITY;
        mx = fmaxf(mx, v[i]);
    }
    mx = block_reduce(mx, true);
    float sum = 0.f;
#pragma unroll
    for (int i = 0; i < 7; i++) {
        int idx = t + i*256;
        if (idx < PP) { v[i] = __expf(v[i] - mx); sum += v[i]; }
    }
    sum = block_reduce(sum, false);
    const float inv = 1.f / sum;
#pragma unroll
    for (int i = 0; i < 7; i++) {
        int idx = t + i*256;
        if (idx < PP) {
            float a = v[i] * inv;
            __half h = __float2half_rn(a);
            __half l = __float2half_rn(a - __half2float(h));
            hrow[idx] = h; lrow[idx] = l;
        }
    }
}

// ============ split / transpose prep kernels ============
__device__ __forceinline__ void hsplit(float v, __half* h, __half* l) {
    __half hh = __float2half_rn(v);
    *h = hh;
    *l = __float2half_rn(v - __half2float(hh));
}

// tiled transpose-split: src[z][c][p] fp32 -> dst[z][p][c] fp16 H/L
// grid (50, 8, 12), block (32, 8)
__global__ __launch_bounds__(256) void tsplit(const float* __restrict__ src,
                                              __half* __restrict__ dh,
                                              __half* __restrict__ dl) {
    __shared__ float tile[32][33];
    const int z = blockIdx.z, p0 = blockIdx.x*32, c0 = blockIdx.y*32;
    const int tx = threadIdx.x, ty = threadIdx.y;
    const float* s = src + (size_t)z*CP;
#pragma unroll
    for (int k = 0; k < 4; k++)
        tile[ty + 8*k][tx] = s[(size_t)(c0 + ty + 8*k)*PP + p0 + tx];
    __syncthreads();
#pragma unroll
    for (int k = 0; k < 4; k++) {
        float v = tile[tx][ty + 8*k];
        size_t o = ((size_t)z*PP + p0 + ty + 8*k)*256 + c0 + tx;
        hsplit(v, &dh[o], &dl[o]);
    }
}

// aggT (H only): agg = msg[e=2n] + msg[e=2n+1] for node n, -> [z][p][c]
// g_msg layout [e*BB+b][c][p]; z = n*4+b -> edge slices 8n+b and 8n+4+b.
__global__ __launch_bounds__(256) void aggT_t() {
    __shared__ float tile[32][33];
    const int z = blockIdx.z, p0 = blockIdx.x*32, c0 = blockIdx.y*32;
    const int n = z >> 2, b = z & 3;
    const int tx = threadIdx.x, ty = threadIdx.y;
    const float* m1 = g_msg + (size_t)(8*n + b)*CP;
    const float* m2 = g_msg + (size_t)(8*n + 4 + b)*CP;
#pragma unroll
    for (int k = 0; k < 4; k++) {
        size_t o = (size_t)(c0 + ty + 8*k)*PP + p0 + tx;
        tile[ty + 8*k][tx] = m1[o] + m2[o];
    }
    __syncthreads();
#pragma unroll
    for (int k = 0; k < 4; k++) {
        size_t o = ((size_t)z*PP + p0 + ty + 8*k)*256 + c0 + tx;
        g_aggTH[o] = __float2half_rn(tile[tx][ty + 8*k]);
    }
}

// rhT (H only): rh = sigmoid(gates_r) * h -> [z][p][c]
__global__ __launch_bounds__(256) void rhT_t() {
    __shared__ float tile[32][33];
    const int z = blockIdx.z, p0 = blockIdx.x*32, c0 = blockIdx.y*32;
    const int tx = threadIdx.x, ty = threadIdx.y;
    const float* gp = g_gates + (size_t)z*512*PP;
    const float* hp = g_nodes + (size_t)z*CP;
#pragma unroll
    for (int k = 0; k < 4; k++) {
        size_t o = (size_t)(c0 + ty + 8*k)*PP + p0 + tx;
        float g = gp[o];
        float r = 1.f / (1.f + __expf(-g));
        tile[ty + 8*k][tx] = r * hp[o];
    }
    __syncthreads();
#pragma unroll
    for (int k = 0; k < 4; k++) {
        size_t o = ((size_t)z*PP + p0 + ty + 8*k)*256 + c0 + tx;
        g_rhTH[o] = __float2half_rn(tile[tx][ty + 8*k]);
    }
}

// unordered pair sums, K-major [pair*b][c][q] (no transpose needed)
__global__ __launch_bounds__(256) void sum_split() {
    size_t i = (size_t)blockIdx.x*256 + threadIdx.x;
    if (i >= (size_t)NN*BCP) return;
    int z2 = (int)(i / CP); size_t cp = i % CP;
    int pr = z2 >> 2, b = z2 & 3;
    float v = g_nodes[(size_t)(c_p0[pr]*BB + b)*CP + cp] +
              g_nodes[(size_t)(c_p1[pr]*BB + b)*CP + cp];
    hsplit(v, &g_sumH[i], &g_sumL[i]);
}

__global__ __launch_bounds__(256) void update_kernel() {
    size_t i = (size_t)blockIdx.x*256 + threadIdx.x;
    if (i >= (size_t)NBCP) return;
    size_t nb = i / CP, cp = i % CP;
    float gz = g_gates[nb*(size_t)(512*PP) + (size_t)CC*PP + cp];
    float zv = 1.f / (1.f + __expf(-gz));
    float h = g_nodes[i];
    float cd = tanhf(g_cand[i]);
    g_nodes[i] = (1.f - zv)*h + zv*cd;
}

// w[oc][ci][3][3] -> [s][oc][ci] fp16 hi/lo
__global__ __launch_bounds__(256) void wsplit(const float* __restrict__ w,
                                              __half* __restrict__ dh,
                                              __half* __restrict__ dl, int OC) {
    size_t i = (size_t)blockIdx.x*256 + threadIdx.x;
    size_t total = (size_t)9*OC*512;
    if (i >= total) return;
    int ci = (int)(i & 511);
    int oc = (int)((i >> 9) % OC);
    int s  = (int)(i / ((size_t)OC*512));
    float v = w[((size_t)oc*512 + ci)*9 + s];
    hsplit(v, &dh[i], &dl[i]);
}

__global__ __launch_bounds__(256) void copy_in(const float* __restrict__ src) {
    size_t i = (size_t)blockIdx.x*256 + threadIdx.x;
    if (i < (size_t)NBCP/4) ((float4*)g_nodes)[i] = ((const float4*)src)[i];
}
__global__ __launch_bounds__(256) void copy_out(float* __restrict__ dst) {
    size_t i = (size_t)blockIdx.x*256 + threadIdx.x;
    if (i < (size_t)NBCP/4) ((float4*)dst)[i] = ((const float4*)g_nodes)[i];
}

// ---------------- host launch ----------------
extern "C" void kernel_launch(void* const* d_in, const int* in_sizes, int n_in,
                              void* d_out, int out_size) {
    const float* in_nodes = (const float*)d_in[0];
    const float* theta_w  = (const float*)d_in[1];
    const float* theta_b  = (const float*)d_in[2];
    const float* gw       = (const float*)d_in[3];
    const float* gb       = (const float*)d_in[4];
    const float* cw       = (const float*)d_in[5];
    const float* cb       = (const float*)d_in[6];
    float* out = (float*)d_out;

    __half *p_wgH, *p_wgL, *p_wcH, *p_wcL, *p_nTH, *p_nTL, *p_rhH, *p_thH, *p_thL;
    float *p_nodes, *p_th, *p_gates, *p_cand;
    cudaGetSymbolAddress((void**)&p_wgH, g_wgH);
    cudaGetSymbolAddress((void**)&p_wgL, g_wgL);
    cudaGetSymbolAddress((void**)&p_wcH, g_wcH);
    cudaGetSymbolAddress((void**)&p_wcL, g_wcL);
    cudaGetSymbolAddress((void**)&p_nTH, g_nodesTH);
    cudaGetSymbolAddress((void**)&p_nTL, g_nodesTL);
    cudaGetSymbolAddress((void**)&p_rhH, g_rhTH);
    cudaGetSymbolAddress((void**)&p_thH, g_thTH);
    cudaGetSymbolAddress((void**)&p_thL, g_thTL);
    cudaGetSymbolAddress((void**)&p_nodes, g_nodes);
    cudaGetSymbolAddress((void**)&p_th,    g_th);
    cudaGetSymbolAddress((void**)&p_gates, g_gates);
    cudaGetSymbolAddress((void**)&p_cand,  g_cand);

    copy_in<<<(NBCP/4 + 255)/256, 256>>>(in_nodes);
    wsplit<<<((size_t)9*512*512 + 255)/256, 256>>>(gw, p_wgH, p_wgL, 512);
    wsplit<<<((size_t)9*256*512 + 255)/256, 256>>>(cw, p_wcH, p_wcL, 256);

    const int EW = NBCP/256;  // 19200
    const dim3 tgrid(50, 8, 12), tblk(32, 8);
    for (int pass = 0; pass < 2; pass++) {
        theta_gemm <<<dim3(13, 2, NBB), 256>>>(theta_w, theta_b);
        tsplit<<<tgrid, tblk>>>(p_nodes, p_nTH, p_nTL);
        tsplit<<<tgrid, tblk>>>(p_th, p_thH, p_thL);
        sum_split<<<EW, 256>>>();
        scores_mma<<<dim3(13, 13, EE*BB), 256>>>();
        softmax_fp<<<EE*BB*PP, 256>>>();
        msg_mma<<<dim3(13, 2, EE*BB), 256>>>();
        aggT_t<<<tgrid, tblk>>>();
        conv_mma<<<dim3(13, 4, NBB), 256>>>(p_wgH, p_wgL, gb, p_nTH, p_gates, 512);
        rhT_t<<<tgrid, tblk>>>();
        conv_mma<<<dim3(13, 2, NBB), 256>>>(p_wcH, p_wcL, cb, p_rhH, p_cand, 256);
        update_kernel<<<EW, 256>>>();
    }
    copy_out<<<(NBCP/4 + 255)/256, 256>>>(out);
}

// round 7
// speedup vs baseline: 3.4188x; 1.0838x over previous
#include <cuda_runtime.h>
#include <cuda_fp16.h>
#include <math.h>
#include <stdint.h>

// ---------------- problem constants ----------------
#define NN   3
#define BB   4
#define CC   256
#define HH   40
#define WW   40
#define PP   (HH*WW)           // 1600
#define EE   6
#define NBB  (NN*BB)           // 12
#define CP   (CC*PP)           // 409600
#define BCP  (BB*CP)
#define NBCP (NN*BCP)          // 4915200

// ---------------- scratch ----------------
__device__ float g_nodes [NBCP];
__device__ float g_scores[(size_t)EE*BB*PP*PP];
__device__ float g_msg   [(size_t)EE*BCP];
__device__ float g_gates [(size_t)NBB*512*PP];
__device__ float g_cand  [NBCP];

// fp16 hi/lo split buffers (16B-aligned for cp.async)
__device__ __align__(16) __half g_atnH[(size_t)EE*BB*PP*PP];
__device__ __align__(16) __half g_atnL[(size_t)EE*BB*PP*PP];
__device__ __align__(16) __half g_nodesTH[NBCP], g_nodesTL[NBCP]; // [z][p][c]
__device__ __align__(16) __half g_thTH[NBCP],    g_thTL[NBCP];    // [z][p][c]
__device__ __align__(16) __half g_sumH[NN*BCP],  g_sumL[NN*BCP];  // [pair*b][c][q]
__device__ __align__(16) __half g_aggTH[NBCP];                    // [z][p][c] (H only)
__device__ __align__(16) __half g_rhTH[NBCP];                     // [z][p][c] (H only)
__device__ __align__(16) __half g_wgH[9*512*512], g_wgL[9*512*512]; // [s][oc][ci]
__device__ __align__(16) __half g_wcH[9*256*512], g_wcL[9*256*512];
__device__ __align__(16) __half g_wtH[CC*CC],     g_wtL[CC*CC];     // theta W [o][c]

__device__ __constant__ int c_recv[EE] = {0,0,1,1,2,2};
__device__ __constant__ int c_send[EE] = {1,2,0,2,0,1};
__device__ __constant__ int c_pair[EE] = {0,1,0,2,1,2};
__device__ __constant__ int c_p0[NN]   = {0,0,1};
__device__ __constant__ int c_p1[NN]   = {1,2,2};

// ================= low-level helpers (portable PTX only) =================
__device__ __forceinline__ uint32_t smem_u32(const void* p) {
    uint32_t a;
    asm("{ .reg .u64 t; cvta.to.shared.u64 t, %1; cvt.u32.u64 %0, t; }" : "=r"(a) : "l"(p));
    return a;
}
__device__ __forceinline__ void cp16(uint32_t dst, const void* src, bool v) {
    asm volatile("cp.async.cg.shared.global [%0], [%1], 16, %2;"
                 :: "r"(dst), "l"(src), "r"(v ? 16 : 0));
}
#define CP_COMMIT() asm volatile("cp.async.commit_group;" ::: "memory")
#define CP_WAIT1()  asm volatile("cp.async.wait_group 1;" ::: "memory")

__device__ __forceinline__ void ldsm4(uint32_t (&r)[4], uint32_t addr) {
    asm volatile("ldmatrix.sync.aligned.m8n8.x4.shared.b16 {%0,%1,%2,%3}, [%4];"
                 : "=r"(r[0]), "=r"(r[1]), "=r"(r[2]), "=r"(r[3]) : "r"(addr));
}
__device__ __forceinline__ void mma16816(float* c, const uint32_t (&a)[4],
                                         uint32_t b0, uint32_t b1) {
    asm volatile("mma.sync.aligned.m16n8k16.row.col.f32.f16.f16.f32 "
                 "{%0,%1,%2,%3}, {%4,%5,%6,%7}, {%8,%9}, {%0,%1,%2,%3};"
                 : "+f"(c[0]), "+f"(c[1]), "+f"(c[2]), "+f"(c[3])
                 : "r"(a[0]), "r"(a[1]), "r"(a[2]), "r"(a[3]), "r"(b0), "r"(b1));
}

// ---------------- tile geometry ----------------
// CTA 256 threads = 8 warps (wm 0..1 x wn 0..3); CTA tile 128x128, BK=64.
// smem tiles [128 rows][72 fp16] (144B stride: conflict-free for 8-row ldmatrix).
#define TSTRIDE 72
#define TILE_B  (128*TSTRIDE*2)   // 18432 bytes per tile buffer

__device__ __forceinline__ void compute_chunk(uint32_t aT, uint32_t bT,
                                              int lane, int wm, int wn,
                                              float (*acc)[4][4]) {
    const int arow = wm*64 + ((lane>>3)&1)*8 + (lane&7);
    const int acol = (lane>>4)*8;
    const int brow = wn*32 + ((lane>>4)&1)*8 + (lane&7);
    const int bcol = ((lane>>3)&1)*8;
#pragma unroll
    for (int ks = 0; ks < 4; ks++) {
        uint32_t a[4][4], b[2][4];
#pragma unroll
        for (int mt = 0; mt < 4; mt++)
            ldsm4(a[mt], aT + (uint32_t)(((arow + mt*16)*TSTRIDE) + acol + ks*16)*2);
#pragma unroll
        for (int np = 0; np < 2; np++)
            ldsm4(b[np], bT + (uint32_t)(((brow + np*16)*TSTRIDE) + bcol + ks*16)*2);
#pragma unroll
        for (int mt = 0; mt < 4; mt++)
#pragma unroll
            for (int nt = 0; nt < 4; nt++)
                mma16816(acc[mt][nt], a[mt], b[nt>>1][(nt&1)*2], b[nt>>1][(nt&1)*2+1]);
    }
}

__device__ __forceinline__ void epilogue(float (*acc)[4][4], float* out,
                                         int m0, int n0, int Mtot, int Ntot,
                                         const float* bias, int lane, int wm, int wn) {
#pragma unroll
    for (int mt = 0; mt < 4; mt++) {
        int m = m0 + wm*64 + mt*16 + (lane>>2);
        float bv0 = (bias && m < Mtot) ? bias[m] : 0.f;
        float bv1 = (bias && m+8 < Mtot) ? bias[m+8] : 0.f;
#pragma unroll
        for (int nt = 0; nt < 4; nt++) {
            int n = n0 + wn*32 + nt*8 + (lane&3)*2;
            if (n >= Ntot) continue;
            if (m < Mtot) {
                float2 v = make_float2(acc[mt][nt][0] + bv0, acc[mt][nt][1] + bv0);
                *(float2*)&out[(size_t)m*Ntot + n] = v;
            }
            if (m+8 < Mtot) {
                float2 v = make_float2(acc[mt][nt][2] + bv1, acc[mt][nt][3] + bv1);
                *(float2*)&out[(size_t)(m+8)*Ntot + n] = v;
            }
        }
    }
}

// ============ scores: S[p][q] = sum_c th[p][c] * nodes[q][c], fp16 3-seg, K'=768 ============
__global__ __launch_bounds__(256) void scores_mma() {
    __shared__ alignas(16) __half As[3][128][TSTRIDE];
    __shared__ alignas(16) __half Bs[3][128][TSTRIDE];
    const int tid = threadIdx.x, lane = tid & 31, wid = tid >> 5;
    const int wm = wid & 1, wn = wid >> 1;
    const int z = blockIdx.z, e = z >> 2, b = z & 3;
    const int zr = c_recv[e]*BB + b, zs = c_send[e]*BB + b;
    const int m0 = blockIdx.y*128, n0 = blockIdx.x*128;
    float* Cp = g_scores + (size_t)z*PP*PP;
    const uint32_t sA = smem_u32(As), sB = smem_u32(Bs);

    const int r0 = tid >> 2, seg8 = (tid & 3)*8;
    float acc[4][4][4] = {};

    auto stage = [&](int t, int buf) {
        int sg = t >> 2, k0 = (t & 3)*64;
        const __half* aS = (sg == 1) ? g_thTL : g_thTH;
        const __half* bS = (sg == 2) ? g_nodesTL : g_nodesTH;
        uint32_t aT = sA + buf*TILE_B, bT = sB + buf*TILE_B;
#pragma unroll
        for (int i = 0; i < 2; i++) {
            int row = r0 + i*64;
            int gm = m0 + row, gn = n0 + row;
            bool va = gm < PP, vb = gn < PP;
            const __half* pa = aS + ((size_t)zr*PP + (va ? gm : 0))*256 + k0;
            const __half* pb = bS + ((size_t)zs*PP + (vb ? gn : 0))*256 + k0;
#pragma unroll
            for (int j = 0; j < 2; j++) {
                int koff = seg8 + j*32;
                uint32_t o = (uint32_t)(row*TSTRIDE + koff)*2;
                cp16(aT + o, pa + koff, va);
                cp16(bT + o, pb + koff, vb);
            }
        }
    };

    const int NT = 12;
    stage(0, 0); CP_COMMIT();
    stage(1, 1); CP_COMMIT();
    for (int t = 0; t < NT; t++) {
        CP_WAIT1(); __syncthreads();
        if (t+2 < NT) { stage(t+2, (t+2)%3); CP_COMMIT(); }
        compute_chunk(sA + (t%3)*TILE_B, sB + (t%3)*TILE_B, lane, wm, wn, acc);
        __syncthreads();
    }
    epilogue(acc, Cp, m0, n0, PP, PP, nullptr, lane, wm, wn);
}

// ============ msg: M[c][p] = sum_q sum[c][q] * atn[p][q], fp16 3-seg, K'=4800 ============
__global__ __launch_bounds__(256) void msg_mma() {
    __shared__ alignas(16) __half As[3][128][TSTRIDE];
    __shared__ alignas(16) __half Bs[3][128][TSTRIDE];
    const int tid = threadIdx.x, lane = tid & 31, wid = tid >> 5;
    const int wm = wid & 1, wn = wid >> 1;
    const int z = blockIdx.z, e = z >> 2, b = z & 3;
    const int zp = c_pair[e]*BB + b;
    const int m0 = blockIdx.y*128, n0 = blockIdx.x*128;
    float* Cp = g_msg + (size_t)z*CP;
    const uint32_t sA = smem_u32(As), sB = smem_u32(Bs);

    const int r0 = tid >> 2, seg8 = (tid & 3)*8;
    float acc[4][4][4] = {};

    auto stage = [&](int t, int buf) {
        int sg = t / 25, k0 = (t % 25)*64;
        const __half* aS = (sg == 1) ? g_sumL : g_sumH;
        const __half* bS = (sg == 2) ? g_atnL : g_atnH;
        uint32_t aT = sA + buf*TILE_B, bT = sB + buf*TILE_B;
#pragma unroll
        for (int i = 0; i < 2; i++) {
            int row = r0 + i*64;
            int gn = n0 + row;
            bool vb = gn < PP;
            const __half* pa = aS + ((size_t)zp*CC + m0 + row)*PP + k0;
            const __half* pb = bS + ((size_t)z*PP + (vb ? gn : 0))*PP + k0;
#pragma unroll
            for (int j = 0; j < 2; j++) {
                int koff = seg8 + j*32;
                uint32_t o = (uint32_t)(row*TSTRIDE + koff)*2;
                cp16(aT + o, pa + koff, true);
                cp16(bT + o, pb + koff, vb);
            }
        }
    };

    const int NT = 75;
    stage(0, 0); CP_COMMIT();
    stage(1, 1); CP_COMMIT();
    for (int t = 0; t < NT; t++) {
        CP_WAIT1(); __syncthreads();
        if (t+2 < NT) { stage(t+2, (t+2)%3); CP_COMMIT(); }
        compute_chunk(sA + (t%3)*TILE_B, sB + (t%3)*TILE_B, lane, wm, wn, acc);
        __syncthreads();
    }
    epilogue(acc, Cp, m0, n0, CC, PP, nullptr, lane, wm, wn);
}

// ============ conv3x3 as GEMM: fp16 2-seg ([wH|wL]*[xH|xH]), K' = 2*4608 = 9216 ============
__global__ __launch_bounds__(256) void conv_mma(const __half* __restrict__ wH,
                                                const __half* __restrict__ wL,
                                                const float* __restrict__ bias,
                                                const __half* __restrict__ x1H,
                                                float* __restrict__ out, int OC) {
    __shared__ alignas(16) __half As[3][128][TSTRIDE];
    __shared__ alignas(16) __half Bs[3][128][TSTRIDE];
    const int tid = threadIdx.x, lane = tid & 31, wid = tid >> 5;
    const int wm = wid & 1, wn = wid >> 1;
    const int z = blockIdx.z;
    const int m0 = blockIdx.y*128, n0 = blockIdx.x*128;
    float* pO = out + (size_t)z*OC*PP;
    const uint32_t sA = smem_u32(As), sB = smem_u32(Bs);

    const int r0 = tid >> 2, seg8 = (tid & 3)*8;
    int gn0 = n0 + r0,        y0 = gn0 / WW, x0 = gn0 % WW;
    int gn1 = n0 + r0 + 64,   y1 = gn1 / WW, x1c = gn1 % WW;
    float acc[4][4][4] = {};

    auto stage = [&](int t, int buf) {
        int sg = t / 72;                 // 0: wH, 1: wL  (B always H)
        int kk = (t % 72)*64;
        int s  = kk >> 9;
        int cw = kk & 511;               // 0,64,...,448
        int ky = s/3 - 1, kx = s%3 - 1;
        const __half* aS = (sg == 1) ? wL : wH;
        const __half* bS = (cw < 256) ? g_aggTH : x1H;
        int ci = cw & 255;
        uint32_t aT = sA + buf*TILE_B, bT = sB + buf*TILE_B;
#pragma unroll
        for (int i = 0; i < 2; i++) {
            int row = r0 + i*64;
            const __half* pa = aS + ((size_t)s*OC + m0 + row)*512 + cw;
            int yy = (i ? y1 : y0) + ky, xx = (i ? x1c : x0) + kx;
            int gnr = i ? gn1 : gn0;
            bool vb = (gnr < PP) && yy >= 0 && yy < HH && xx >= 0 && xx < WW;
            int sp = vb ? (yy*WW + xx) : 0;
            const __half* pb = bS + ((size_t)z*PP + sp)*256 + ci;
#pragma unroll
            for (int j = 0; j < 2; j++) {
                int koff = seg8 + j*32;
                uint32_t o = (uint32_t)(row*TSTRIDE + koff)*2;
                cp16(aT + o, pa + koff, true);
                cp16(bT + o, pb + koff, vb);
            }
        }
    };

    const int NT = 144;
    stage(0, 0); CP_COMMIT();
    stage(1, 1); CP_COMMIT();
    for (int t = 0; t < NT; t++) {
        CP_WAIT1(); __syncthreads();
        if (t+2 < NT) { stage(t+2, (t+2)%3); CP_COMMIT(); }
        compute_chunk(sA + (t%3)*TILE_B, sB + (t%3)*TILE_B, lane, wm, wn, acc);
        __syncthreads();
    }
    epilogue(acc, pO, m0, n0, OC, PP, bias, lane, wm, wn);
}

// ============ theta via HMMA: thT[p][o] = sum_c nodesT[p][c]*W[o][c] + b[o], 3-seg ============
// Epilogue splits fp32 -> fp16 H/L and writes thTH/thTL directly. Bias is per-COLUMN (o).
__global__ __launch_bounds__(256) void theta_mma(const float* __restrict__ bias) {
    __shared__ alignas(16) __half As[3][128][TSTRIDE];
    __shared__ alignas(16) __half Bs[3][128][TSTRIDE];
    const int tid = threadIdx.x, lane = tid & 31, wid = tid >> 5;
    const int wm = wid & 1, wn = wid >> 1;
    const int z = blockIdx.z;
    const int m0 = blockIdx.y*128, n0 = blockIdx.x*128;
    const uint32_t sA = smem_u32(As), sB = smem_u32(Bs);

    const int r0 = tid >> 2, seg8 = (tid & 3)*8;
    float acc[4][4][4] = {};

    auto stage = [&](int t, int buf) {
        int sg = t >> 2, k0 = (t & 3)*64;
        const __half* aS = (sg == 1) ? g_nodesTL : g_nodesTH;
        const __half* bS = (sg == 2) ? g_wtL : g_wtH;
        uint32_t aT = sA + buf*TILE_B, bT = sB + buf*TILE_B;
#pragma unroll
        for (int i = 0; i < 2; i++) {
            int row = r0 + i*64;
            int gm = m0 + row;
            bool va = gm < PP;
            const __half* pa = aS + ((size_t)z*PP + (va ? gm : 0))*256 + k0;
            const __half* pb = bS + (size_t)(n0 + row)*256 + k0;
#pragma unroll
            for (int j = 0; j < 2; j++) {
                int koff = seg8 + j*32;
                uint32_t o = (uint32_t)(row*TSTRIDE + koff)*2;
                cp16(aT + o, pa + koff, va);
                cp16(bT + o, pb + koff, true);
            }
        }
    };

    const int NT = 12;
    stage(0, 0); CP_COMMIT();
    stage(1, 1); CP_COMMIT();
    for (int t = 0; t < NT; t++) {
        CP_WAIT1(); __syncthreads();
        if (t+2 < NT) { stage(t+2, (t+2)%3); CP_COMMIT(); }
        compute_chunk(sA + (t%3)*TILE_B, sB + (t%3)*TILE_B, lane, wm, wn, acc);
        __syncthreads();
    }

    // split epilogue -> thTH/thTL [z][p][c]
#pragma unroll
    for (int mt = 0; mt < 4; mt++) {
        int m = m0 + wm*64 + mt*16 + (lane>>2);
#pragma unroll
        for (int nt = 0; nt < 4; nt++) {
            int n = n0 + wn*32 + nt*8 + (lane&3)*2;
            float bv0 = bias[n], bv1 = bias[n+1];
#pragma unroll
            for (int half = 0; half < 2; half++) {
                int mm = m + half*8;
                if (mm >= PP) continue;
                float v0 = acc[mt][nt][half*2+0] + bv0;
                float v1 = acc[mt][nt][half*2+1] + bv1;
                __half h0 = __float2half_rn(v0);
                __half h1 = __float2half_rn(v1);
                __half l0 = __float2half_rn(v0 - __half2float(h0));
                __half l1 = __float2half_rn(v1 - __half2float(h1));
                size_t o = ((size_t)z*PP + mm)*256 + n;
                *(__half2*)&g_thTH[o] = __halves2half2(h0, h1);
                *(__half2*)&g_thTL[o] = __halves2half2(l0, l1);
            }
        }
    }
}

// ============ softmax rows -> fp16 hi/lo attention ============
__device__ __forceinline__ float block_reduce(float v, bool is_max) {
    __shared__ float s[32];
    __syncthreads();
#pragma unroll
    for (int o = 16; o > 0; o >>= 1) {
        float t = __shfl_xor_sync(0xffffffffu, v, o);
        v = is_max ? fmaxf(v, t) : (v + t);
    }
    const int w = threadIdx.x >> 5, l = threadIdx.x & 31;
    if (l == 0) s[w] = v;
    __syncthreads();
    if (w == 0) {
        v = (l < 8) ? s[l] : (is_max ? -INFINITY : 0.f);
#pragma unroll
        for (int o = 4; o > 0; o >>= 1) {
            float t = __shfl_xor_sync(0xffffffffu, v, o);
            v = is_max ? fmaxf(v, t) : (v + t);
        }
        if (l == 0) s[0] = v;
    }
    __syncthreads();
    return s[0];
}

__global__ __launch_bounds__(256) void softmax_fp() {
    const size_t row = blockIdx.x;
    const float* srow = g_scores + row*PP;
    __half* hrow = g_atnH + row*PP;
    __half* lrow = g_atnL + row*PP;
    const int t = threadIdx.x;
    float v[7];
    float mx = -INFINITY;
#pragma unroll
    for (int i = 0; i < 7; i++) {
        int idx = t + i*256;
        v[i] = (idx < PP) ? srow[idx] : -INFINITY;
        mx = fmaxf(mx, v[i]);
    }
    mx = block_reduce(mx, true);
    float sum = 0.f;
#pragma unroll
    for (int i = 0; i < 7; i++) {
        int idx = t + i*256;
        if (idx < PP) { v[i] = __expf(v[i] - mx); sum += v[i]; }
    }
    sum = block_reduce(sum, false);
    const float inv = 1.f / sum;
#pragma unroll
    for (int i = 0; i < 7; i++) {
        int idx = t + i*256;
        if (idx < PP) {
            float a = v[i] * inv;
            __half h = __float2half_rn(a);
            __half l = __float2half_rn(a - __half2float(h));
            hrow[idx] = h; lrow[idx] = l;
        }
    }
}

// ============ split / transpose prep kernels ============
__device__ __forceinline__ void hsplit(float v, __half* h, __half* l) {
    __half hh = __float2half_rn(v);
    *h = hh;
    *l = __float2half_rn(v - __half2float(hh));
}

// tiled transpose-split: src[z][c][p] fp32 -> dst[z][p][c] fp16 H/L
__global__ __launch_bounds__(256) void tsplit(const float* __restrict__ src,
                                              __half* __restrict__ dh,
                                              __half* __restrict__ dl) {
    __shared__ float tile[32][33];
    const int z = blockIdx.z, p0 = blockIdx.x*32, c0 = blockIdx.y*32;
    const int tx = threadIdx.x, ty = threadIdx.y;
    const float* s = src + (size_t)z*CP;
#pragma unroll
    for (int k = 0; k < 4; k++)
        tile[ty + 8*k][tx] = s[(size_t)(c0 + ty + 8*k)*PP + p0 + tx];
    __syncthreads();
#pragma unroll
    for (int k = 0; k < 4; k++) {
        float v = tile[tx][ty + 8*k];
        size_t o = ((size_t)z*PP + p0 + ty + 8*k)*256 + c0 + tx;
        hsplit(v, &dh[o], &dl[o]);
    }
}

// aggT (H only): agg = msg[e=2n]+msg[e=2n+1], -> [z][p][c]; msg layout [e*BB+b][c][p]
__global__ __launch_bounds__(256) void aggT_t() {
    __shared__ float tile[32][33];
    const int z = blockIdx.z, p0 = blockIdx.x*32, c0 = blockIdx.y*32;
    const int n = z >> 2, b = z & 3;
    const int tx = threadIdx.x, ty = threadIdx.y;
    const float* m1 = g_msg + (size_t)(8*n + b)*CP;
    const float* m2 = g_msg + (size_t)(8*n + 4 + b)*CP;
#pragma unroll
    for (int k = 0; k < 4; k++) {
        size_t o = (size_t)(c0 + ty + 8*k)*PP + p0 + tx;
        tile[ty + 8*k][tx] = m1[o] + m2[o];
    }
    __syncthreads();
#pragma unroll
    for (int k = 0; k < 4; k++) {
        size_t o = ((size_t)z*PP + p0 + ty + 8*k)*256 + c0 + tx;
        g_aggTH[o] = __float2half_rn(tile[tx][ty + 8*k]);
    }
}

// rhT (H only): rh = sigmoid(gates_r) * h -> [z][p][c]
__global__ __launch_bounds__(256) void rhT_t() {
    __shared__ float tile[32][33];
    const int z = blockIdx.z, p0 = blockIdx.x*32, c0 = blockIdx.y*32;
    const int tx = threadIdx.x, ty = threadIdx.y;
    const float* gp = g_gates + (size_t)z*512*PP;
    const float* hp = g_nodes + (size_t)z*CP;
#pragma unroll
    for (int k = 0; k < 4; k++) {
        size_t o = (size_t)(c0 + ty + 8*k)*PP + p0 + tx;
        float g = gp[o];
        float r = 1.f / (1.f + __expf(-g));
        tile[ty + 8*k][tx] = r * hp[o];
    }
    __syncthreads();
#pragma unroll
    for (int k = 0; k < 4; k++) {
        size_t o = ((size_t)z*PP + p0 + ty + 8*k)*256 + c0 + tx;
        g_rhTH[o] = __float2half_rn(tile[tx][ty + 8*k]);
    }
}

// unordered pair sums, K-major [pair*b][c][q]
__global__ __launch_bounds__(256) void sum_split() {
    size_t i = (size_t)blockIdx.x*256 + threadIdx.x;
    if (i >= (size_t)NN*BCP) return;
    int z2 = (int)(i / CP); size_t cp = i % CP;
    int pr = z2 >> 2, b = z2 & 3;
    float v = g_nodes[(size_t)(c_p0[pr]*BB + b)*CP + cp] +
              g_nodes[(size_t)(c_p1[pr]*BB + b)*CP + cp];
    hsplit(v, &g_sumH[i], &g_sumL[i]);
}

__global__ __launch_bounds__(256) void update_kernel() {
    size_t i = (size_t)blockIdx.x*256 + threadIdx.x;
    if (i >= (size_t)NBCP) return;
    size_t nb = i / CP, cp = i % CP;
    float gz = g_gates[nb*(size_t)(512*PP) + (size_t)CC*PP + cp];
    float zv = 1.f / (1.f + __expf(-gz));
    float h = g_nodes[i];
    float cd = tanhf(g_cand[i]);
    g_nodes[i] = (1.f - zv)*h + zv*cd;
}

// conv weights: w[oc][ci][3][3] -> [s][oc][ci] fp16 hi/lo
__global__ __launch_bounds__(256) void wsplit(const float* __restrict__ w,
                                              __half* __restrict__ dh,
                                              __half* __restrict__ dl, int OC) {
    size_t i = (size_t)blockIdx.x*256 + threadIdx.x;
    size_t total = (size_t)9*OC*512;
    if (i >= total) return;
    int ci = (int)(i & 511);
    int oc = (int)((i >> 9) % OC);
    int s  = (int)(i / ((size_t)OC*512));
    float v = w[((size_t)oc*512 + ci)*9 + s];
    hsplit(v, &dh[i], &dl[i]);
}

// theta weights: W [o][c] fp32 -> fp16 hi/lo (same layout)
__global__ __launch_bounds__(256) void wtheta_split(const float* __restrict__ w) {
    int i = blockIdx.x*256 + threadIdx.x;
    if (i >= CC*CC) return;
    hsplit(w[i], &g_wtH[i], &g_wtL[i]);
}

__global__ __launch_bounds__(256) void copy_in(const float* __restrict__ src) {
    size_t i = (size_t)blockIdx.x*256 + threadIdx.x;
    if (i < (size_t)NBCP/4) ((float4*)g_nodes)[i] = ((const float4*)src)[i];
}
__global__ __launch_bounds__(256) void copy_out(float* __restrict__ dst) {
    size_t i = (size_t)blockIdx.x*256 + threadIdx.x;
    if (i < (size_t)NBCP/4) ((float4*)dst)[i] = ((const float4*)g_nodes)[i];
}

// ---------------- host launch ----------------
extern "C" void kernel_launch(void* const* d_in, const int* in_sizes, int n_in,
                              void* d_out, int out_size) {
    const float* in_nodes = (const float*)d_in[0];
    const float* theta_w  = (const float*)d_in[1];
    const float* theta_b  = (const float*)d_in[2];
    const float* gw       = (const float*)d_in[3];
    const float* gb       = (const float*)d_in[4];
    const float* cw       = (const float*)d_in[5];
    const float* cb       = (const float*)d_in[6];
    float* out = (float*)d_out;

    __half *p_wgH, *p_wgL, *p_wcH, *p_wcL, *p_nTH, *p_nTL, *p_rhH;
    float *p_nodes, *p_gates, *p_cand;
    cudaGetSymbolAddress((void**)&p_wgH, g_wgH);
    cudaGetSymbolAddress((void**)&p_wgL, g_wgL);
    cudaGetSymbolAddress((void**)&p_wcH, g_wcH);
    cudaGetSymbolAddress((void**)&p_wcL, g_wcL);
    cudaGetSymbolAddress((void**)&p_nTH, g_nodesTH);
    cudaGetSymbolAddress((void**)&p_nTL, g_nodesTL);
    cudaGetSymbolAddress((void**)&p_rhH, g_rhTH);
    cudaGetSymbolAddress((void**)&p_nodes, g_nodes);
    cudaGetSymbolAddress((void**)&p_gates, g_gates);
    cudaGetSymbolAddress((void**)&p_cand,  g_cand);

    copy_in<<<(NBCP/4 + 255)/256, 256>>>(in_nodes);
    wsplit<<<((size_t)9*512*512 + 255)/256, 256>>>(gw, p_wgH, p_wgL, 512);
    wsplit<<<((size_t)9*256*512 + 255)/256, 256>>>(cw, p_wcH, p_wcL, 256);
    wtheta_split<<<(CC*CC + 255)/256, 256>>>(theta_w);

    const int EW = NBCP/256;  // 19200
    const dim3 tgrid(50, 8, 12), tblk(32, 8);
    for (int pass = 0; pass < 2; pass++) {
        tsplit<<<tgrid, tblk>>>(p_nodes, p_nTH, p_nTL);
        theta_mma<<<dim3(2, 13, NBB), 256>>>(theta_b);
        sum_split<<<EW, 256>>>();
        scores_mma<<<dim3(13, 13, EE*BB), 256>>>();
        softmax_fp<<<EE*BB*PP, 256>>>();
        msg_mma<<<dim3(13, 2, EE*BB), 256>>>();
        aggT_t<<<tgrid, tblk>>>();
        conv_mma<<<dim3(13, 4, NBB), 256>>>(p_wgH, p_wgL, gb, p_nTH, p_gates, 512);
        rhT_t<<<tgrid, tblk>>>();
        conv_mma<<<dim3(13, 2, NBB), 256>>>(p_wcH, p_wcL, cb, p_rhH, p_cand, 256);
        update_kernel<<<EW, 256>>>();
    }
    copy_out<<<(NBCP/4 + 255)/256, 256>>>(out);
}